// round 2
// baseline (speedup 1.0000x reference)
#include <cuda_runtime.h>
#include <cuda_bf16.h>
#include <math.h>

// ---------------------------------------------------------------------------
// FlowEncoder: fp32 direct-conv implementation, fused BN+ReLU, graph-capturable.
// Shapes: B=32, img 3x384x512
//   conv1 7x7 s2 p3  ->  32x192x256
//   conv2 5x5 s2 p2  ->  64x96x128
//   conv3 3x3 s2 p1  -> 128x48x64
//   corr (d=4)       ->  81x48x64   (on L2-normalized features, fused)
//   concat [corr,f1] -> 209x48x64
//   convf1 3x3 s2 p1 -> 256x24x32
//   convf2 3x3 s1 p1 -> 256x24x32
//   mean(H,W)        -> (32,256)
//
// No host-side device-memory APIs in kernel_launch: scratch lives in
// __device__ globals referenced directly from device code via a
// compile-time buffer id (no cudaGetSymbolAddress).
// ---------------------------------------------------------------------------

#define BATCH 32

// ------------------------- device scratch (no allocs) ----------------------
__device__ float g_bufA[(size_t)BATCH * 32 * 192 * 256];   // conv1 out
__device__ float g_bufB[(size_t)BATCH * 64 * 96 * 128];    // conv2 out
__device__ float g_f0[(size_t)BATCH * 128 * 48 * 64];
__device__ float g_f1[(size_t)BATCH * 128 * 48 * 64];
__device__ float g_concat[(size_t)BATCH * 209 * 48 * 64];
__device__ float g_y1[(size_t)BATCH * 256 * 24 * 32];
__device__ float g_y2[(size_t)BATCH * 256 * 24 * 32];
__device__ float g_inv0[(size_t)BATCH * 48 * 64];          // 1/||f0(b,:,h,w)||
__device__ float g_inv1[(size_t)BATCH * 48 * 64];

// folded BN scale/bias, packed: [0:32)=L1, [32:96)=L2, [96:224)=L3,
// [224:480)=F1, [480:736)=F2
__device__ float g_scale[736];
__device__ float g_bias[736];

// Buffer ids (compile-time selection of __device__ scratch)
#define BUF_EXT    0
#define BUF_A      1
#define BUF_B      2
#define BUF_F0     3
#define BUF_F1     4
#define BUF_CONCAT 5
#define BUF_Y1     6
#define BUF_Y2     7

__device__ __forceinline__ float* get_buf(int id, const float* ext) {
    switch (id) {
        case BUF_A:      return g_bufA;
        case BUF_B:      return g_bufB;
        case BUF_F0:     return g_f0;
        case BUF_F1:     return g_f1;
        case BUF_CONCAT: return g_concat;
        case BUF_Y1:     return g_y1;
        case BUF_Y2:     return g_y2;
        default:         return const_cast<float*>(ext);
    }
}

// ------------------------- BN folding -------------------------------------
// bn(conv+b) = conv*s + ((b-m)*s + be),  s = g/sqrt(v+eps)
__global__ void bn_prep_kernel(const float* __restrict__ g, const float* __restrict__ be,
                               const float* __restrict__ m, const float* __restrict__ v,
                               const float* __restrict__ cb,
                               int off, int C) {
    int i = blockIdx.x * blockDim.x + threadIdx.x;
    if (i < C) {
        float s = g[i] / sqrtf(v[i] + 1e-5f);
        g_scale[off + i] = s;
        g_bias[off + i]  = (cb[i] - m[i]) * s + be[i];
    }
}

// ------------------------- fused conv + BN + ReLU --------------------------
// Block: TW x TH threads. Tile: TH x (TW*SPT) outputs, OCB output channels.
// grid.z = B * (OC/OCB)
template <int IC, int OC, int K, int S, int P,
          int TH, int TW, int SPT, int OCB, int ICCH,
          int INBUF, int OUTBUF>
__global__ void __launch_bounds__(TH * TW)
conv_bn_relu_kernel(const float* __restrict__ ext_in, const float* __restrict__ wgt,
                    int bn_off, int IH, int IW, int OH, int OW) {
    constexpr int IN_TH = (TH - 1) * S + K;
    constexpr int IN_TW = (TW * SPT - 1) * S + K;

    __shared__ float sIn[ICCH][IN_TH][IN_TW];
    __shared__ float sW[OCB][ICCH][K][K];

    const float* in = get_buf(INBUF, ext_in);
    float* out      = get_buf(OUTBUF, nullptr);

    const int tx = threadIdx.x, ty = threadIdx.y;
    const int tid = ty * TW + tx;
    const int nthreads = TH * TW;

    const int nOcb = OC / OCB;
    const int b    = blockIdx.z / nOcb;
    const int ocb0 = (blockIdx.z % nOcb) * OCB;
    const int oh0  = blockIdx.y * TH;
    const int ow0  = blockIdx.x * (TW * SPT);
    const int in_r0 = oh0 * S - P;
    const int in_c0 = ow0 * S - P;

    const float* inb = in + (size_t)b * IC * IH * IW;

    float acc[SPT][OCB];
#pragma unroll
    for (int sp = 0; sp < SPT; sp++)
#pragma unroll
        for (int o = 0; o < OCB; o++) acc[sp][o] = 0.f;

    for (int ic0 = 0; ic0 < IC; ic0 += ICCH) {
        // --- load input tile ---
        for (int i = tid; i < ICCH * IN_TH * IN_TW; i += nthreads) {
            int c   = i / (IN_TH * IN_TW);
            int rem = i % (IN_TH * IN_TW);
            int r   = rem / IN_TW;
            int cc  = rem % IN_TW;
            int gch = ic0 + c;
            int gr  = in_r0 + r;
            int gc  = in_c0 + cc;
            float v = 0.f;
            if (gch < IC && gr >= 0 && gr < IH && gc >= 0 && gc < IW)
                v = inb[((size_t)gch * IH + gr) * IW + gc];
            (&sIn[0][0][0])[i] = v;
        }
        // --- load weight chunk ---
        for (int i = tid; i < OCB * ICCH * K * K; i += nthreads) {
            int o   = i / (ICCH * K * K);
            int rem = i % (ICCH * K * K);
            int c   = rem / (K * K);
            int kk  = rem % (K * K);
            int gch = ic0 + c;
            float v = 0.f;
            if (gch < IC)
                v = wgt[((size_t)(ocb0 + o) * IC + gch) * (K * K) + kk];
            (&sW[0][0][0][0])[i] = v;
        }
        __syncthreads();

        // --- accumulate ---
#pragma unroll
        for (int c = 0; c < ICCH; c++) {
#pragma unroll
            for (int ky = 0; ky < K; ky++) {
#pragma unroll
                for (int kx = 0; kx < K; kx++) {
                    float iv[SPT];
#pragma unroll
                    for (int sp = 0; sp < SPT; sp++)
                        iv[sp] = sIn[c][ty * S + ky][(sp * TW + tx) * S + kx];
#pragma unroll
                    for (int o = 0; o < OCB; o++) {
                        float wv = sW[o][c][ky][kx];
#pragma unroll
                        for (int sp = 0; sp < SPT; sp++)
                            acc[sp][o] = fmaf(iv[sp], wv, acc[sp][o]);
                    }
                }
            }
        }
        __syncthreads();
    }

    // --- epilogue: BN + ReLU + store ---
    const int oh = oh0 + ty;
#pragma unroll
    for (int o = 0; o < OCB; o++) {
        int oc  = ocb0 + o;
        float s = g_scale[bn_off + oc];
        float t = g_bias[bn_off + oc];
#pragma unroll
        for (int sp = 0; sp < SPT; sp++) {
            int ow = ow0 + sp * TW + tx;
            float v = fmaf(acc[sp][o], s, t);
            v = fmaxf(v, 0.f);
            out[(((size_t)b * OC + oc) * OH + oh) * OW + ow] = v;
        }
    }
}

// ------------------------- per-pixel inverse L2 norm -----------------------
// f: (B,128,48,64) -> inv: (B,48,64) with inv = 1/max(||f||, eps)
__global__ void l2inv_kernel(int which /*0: f0->inv0, 1: f1->inv1*/) {
    const float* in = which ? g_f1 : g_f0;
    float* inv      = which ? g_inv1 : g_inv0;
    int idx = blockIdx.x * blockDim.x + threadIdx.x;
    const int HW = 48 * 64;
    if (idx >= BATCH * HW) return;
    int b  = idx / HW;
    int hw = idx % HW;
    const float* p = in + (size_t)b * 128 * HW + hw;
    float ss = 0.f;
#pragma unroll 8
    for (int c = 0; c < 128; c++) {
        float v = p[(size_t)c * HW];
        ss = fmaf(v, v, ss);
    }
    inv[idx] = 1.0f / fmaxf(sqrtf(ss), 1e-12f);
}

// ------------------------- correlation volume ------------------------------
// grid = (H=48, B=32), block = 64 (one thread per w). Writes concat[:, 0:81].
// Normalization fused: values scaled by per-pixel inverse norms while staging.
__global__ void __launch_bounds__(64)
corr_kernel() {
    const int H = 48, W = 64, C = 128, HW = H * W;
    const int h = blockIdx.x;
    const int b = blockIdx.y;
    const int w = threadIdx.x;

    __shared__ float sF0[8][9][72];
    __shared__ float sF1[8][64];
    __shared__ float sInv0[9][72];
    __shared__ float sInv1[64];

    float acc[81];
#pragma unroll
    for (int o = 0; o < 81; o++) acc[o] = 0.f;

    const float* f0b = g_f0 + (size_t)b * C * HW;
    const float* f1b = g_f1 + (size_t)b * C * HW;
    const float* inv0b = g_inv0 + (size_t)b * HW;
    const float* inv1b = g_inv1 + (size_t)b * HW;

    // stage inverse norms once
    sInv1[w] = inv1b[h * W + w];
    for (int i = w; i < 9 * 72; i += 64) {
        int r  = i / 72;
        int cc = i % 72;
        int gh = h + r - 4;
        int gw = cc - 4;
        float v = 0.f;
        if (gh >= 0 && gh < H && gw >= 0 && gw < W)
            v = inv0b[gh * W + gw];
        (&sInv0[0][0])[i] = v;
    }
    __syncthreads();

    for (int c0 = 0; c0 < C; c0 += 8) {
        for (int i = w; i < 8 * 64; i += 64) {
            int c = i >> 6, ww = i & 63;
            sF1[c][ww] = f1b[(size_t)(c0 + c) * HW + h * W + ww] * sInv1[ww];
        }
        for (int i = w; i < 8 * 9 * 72; i += 64) {
            int c   = i / (9 * 72);
            int rem = i % (9 * 72);
            int r   = rem / 72;
            int cc  = rem % 72;
            int gh = h + r - 4;
            int gw = cc - 4;
            float v = 0.f;
            if (gh >= 0 && gh < H && gw >= 0 && gw < W)
                v = f0b[(size_t)(c0 + c) * HW + gh * W + gw] * sInv0[r][cc];
            (&sF0[0][0][0])[i] = v;
        }
        __syncthreads();
#pragma unroll
        for (int c = 0; c < 8; c++) {
            float iv = sF1[c][w];
#pragma unroll
            for (int r = 0; r < 9; r++)
#pragma unroll
                for (int d = 0; d < 9; d++)
                    acc[r * 9 + d] = fmaf(sF0[c][r][w + d], iv, acc[r * 9 + d]);
        }
        __syncthreads();
    }
#pragma unroll
    for (int o = 0; o < 81; o++)
        g_concat[(((size_t)b * 209 + o) * H + h) * W + w] = acc[o];
}

// ------------------------- copy raw f1 into concat[:, 81:209] --------------
__global__ void copy_f1_kernel() {
    const int HW = 48 * 64;
    size_t i = (size_t)blockIdx.x * blockDim.x + threadIdx.x;
    size_t total = (size_t)BATCH * 128 * HW;
    if (i >= total) return;
    int b   = (int)(i / (128 * HW));
    int rem = (int)(i % (128 * HW));
    g_concat[(size_t)b * 209 * HW + (size_t)81 * HW + rem] = g_f1[i];
}

// ------------------------- global average pool -----------------------------
// g_y2: (B,256,24,32) -> out (B*256)
__global__ void __launch_bounds__(128)
avgpool_kernel(float* __restrict__ out) {
    __shared__ float sred[4];
    int bo = blockIdx.x;
    const float* p = g_y2 + (size_t)bo * 768;
    float s = 0.f;
    for (int i = threadIdx.x; i < 768; i += 128) s += p[i];
#pragma unroll
    for (int o = 16; o > 0; o >>= 1) s += __shfl_down_sync(0xFFFFFFFFu, s, o);
    if ((threadIdx.x & 31) == 0) sred[threadIdx.x >> 5] = s;
    __syncthreads();
    if (threadIdx.x == 0) {
        float t = sred[0] + sred[1] + sred[2] + sred[3];
        out[bo] = t * (1.0f / 768.0f);
    }
}

// ---------------------------------------------------------------------------
extern "C" void kernel_launch(void* const* d_in, const int* in_sizes, int n_in,
                              void* d_out, int out_size) {
    (void)in_sizes; (void)n_in; (void)out_size;

    const float* img0 = (const float*)d_in[0];
    const float* img1 = (const float*)d_in[1];
    const float* w1 = (const float*)d_in[2];  const float* b1 = (const float*)d_in[3];
    const float* g1 = (const float*)d_in[4];  const float* be1 = (const float*)d_in[5];
    const float* m1 = (const float*)d_in[6];  const float* v1 = (const float*)d_in[7];
    const float* w2 = (const float*)d_in[8];  const float* b2 = (const float*)d_in[9];
    const float* g2 = (const float*)d_in[10]; const float* be2 = (const float*)d_in[11];
    const float* m2 = (const float*)d_in[12]; const float* v2 = (const float*)d_in[13];
    const float* w3 = (const float*)d_in[14]; const float* b3 = (const float*)d_in[15];
    const float* g3 = (const float*)d_in[16]; const float* be3 = (const float*)d_in[17];
    const float* m3 = (const float*)d_in[18]; const float* v3 = (const float*)d_in[19];
    const float* wf1 = (const float*)d_in[20]; const float* bf1 = (const float*)d_in[21];
    const float* gf1 = (const float*)d_in[22]; const float* bef1 = (const float*)d_in[23];
    const float* mf1 = (const float*)d_in[24]; const float* vf1 = (const float*)d_in[25];
    const float* wf2 = (const float*)d_in[26]; const float* bf2 = (const float*)d_in[27];
    const float* gf2 = (const float*)d_in[28]; const float* bef2 = (const float*)d_in[29];
    const float* mf2 = (const float*)d_in[30]; const float* vf2 = (const float*)d_in[31];

    // --- fold BN params (offsets: L1=0, L2=32, L3=96, F1=224, F2=480) ---
    bn_prep_kernel<<<1, 256>>>(g1, be1, m1, v1, b1, 0, 32);
    bn_prep_kernel<<<1, 256>>>(g2, be2, m2, v2, b2, 32, 64);
    bn_prep_kernel<<<1, 256>>>(g3, be3, m3, v3, b3, 96, 128);
    bn_prep_kernel<<<1, 256>>>(gf1, bef1, mf1, vf1, bf1, 224, 256);
    bn_prep_kernel<<<1, 256>>>(gf2, bef2, mf2, vf2, bf2, 480, 256);

    dim3 blk(16, 8);

    // --- backbone img0 -> f0 ---
    conv_bn_relu_kernel<3, 32, 7, 2, 3, 8, 16, 4, 16, 3, BUF_EXT, BUF_A>
        <<<dim3(4, 24, BATCH * 2), blk>>>(img0, w1, 0, 384, 512, 192, 256);
    conv_bn_relu_kernel<32, 64, 5, 2, 2, 8, 16, 4, 16, 4, BUF_A, BUF_B>
        <<<dim3(2, 12, BATCH * 4), blk>>>(nullptr, w2, 32, 192, 256, 96, 128);
    conv_bn_relu_kernel<64, 128, 3, 2, 1, 8, 16, 4, 16, 4, BUF_B, BUF_F0>
        <<<dim3(1, 6, BATCH * 8), blk>>>(nullptr, w3, 96, 96, 128, 48, 64);

    // --- backbone img1 -> f1 ---
    conv_bn_relu_kernel<3, 32, 7, 2, 3, 8, 16, 4, 16, 3, BUF_EXT, BUF_A>
        <<<dim3(4, 24, BATCH * 2), blk>>>(img1, w1, 0, 384, 512, 192, 256);
    conv_bn_relu_kernel<32, 64, 5, 2, 2, 8, 16, 4, 16, 4, BUF_A, BUF_B>
        <<<dim3(2, 12, BATCH * 4), blk>>>(nullptr, w2, 32, 192, 256, 96, 128);
    conv_bn_relu_kernel<64, 128, 3, 2, 1, 8, 16, 4, 16, 4, BUF_B, BUF_F1>
        <<<dim3(1, 6, BATCH * 8), blk>>>(nullptr, w3, 96, 96, 128, 48, 64);

    // --- inverse L2 norms ---
    {
        int n = BATCH * 48 * 64;
        l2inv_kernel<<<(n + 127) / 128, 128>>>(0);
        l2inv_kernel<<<(n + 127) / 128, 128>>>(1);
    }

    // --- correlation -> concat[:, 0:81] ; copy f1 -> concat[:, 81:209] ---
    corr_kernel<<<dim3(48, BATCH), 64>>>();
    {
        size_t n = (size_t)BATCH * 128 * 48 * 64;
        copy_f1_kernel<<<(unsigned)((n + 255) / 256), 256>>>();
    }

    // --- fusion convs ---
    conv_bn_relu_kernel<209, 256, 3, 2, 1, 8, 16, 2, 16, 8, BUF_CONCAT, BUF_Y1>
        <<<dim3(1, 3, BATCH * 16), blk>>>(nullptr, wf1, 224, 48, 64, 24, 32);
    conv_bn_relu_kernel<256, 256, 3, 1, 1, 8, 16, 2, 16, 8, BUF_Y1, BUF_Y2>
        <<<dim3(1, 3, BATCH * 16), blk>>>(nullptr, wf2, 480, 24, 32, 24, 32);

    // --- global average pool -> (B,256) ---
    avgpool_kernel<<<BATCH * 256, 128>>>((float*)d_out);
}

// round 4
// speedup vs baseline: 1.3649x; 1.3649x over previous
#include <cuda_runtime.h>
#include <cuda_bf16.h>
#include <math.h>

// ---------------------------------------------------------------------------
// FlowEncoder — fp32 direct conv with packed f32x2 FMA (FFMA2), fused BN+ReLU.
// Backbone runs both images in one merged batch of 64.
// ---------------------------------------------------------------------------

#define BATCH 32

typedef unsigned long long ull;

// ------------------------- device scratch (no allocs) ----------------------
__device__ float g_bufA[(size_t)64 * 32 * 192 * 256];      // conv1 out (64 images)
__device__ float g_bufB[(size_t)64 * 64 * 96 * 128];       // conv2 out (64 images)
__device__ float g_f0[(size_t)BATCH * 128 * 48 * 64];
__device__ float g_f1[(size_t)BATCH * 128 * 48 * 64];
__device__ float g_concat[(size_t)BATCH * 209 * 48 * 64];
__device__ float g_y1[(size_t)BATCH * 256 * 24 * 32];
__device__ float g_y2[(size_t)BATCH * 256 * 24 * 32];
__device__ float g_inv0[(size_t)BATCH * 48 * 64];
__device__ float g_inv1[(size_t)BATCH * 48 * 64];

// folded BN scale/bias: [0:32)=L1, [32:96)=L2, [96:224)=L3, [224:480)=F1, [480:736)=F2
__device__ float g_scale[736];
__device__ float g_bias[736];

#define BUF_EXT    0
#define BUF_A      1
#define BUF_B      2
#define BUF_F0     3
#define BUF_CONCAT 5
#define BUF_Y1     6
#define BUF_Y2     7

__device__ __forceinline__ float* get_buf(int id) {
    switch (id) {
        case BUF_A:      return g_bufA;
        case BUF_B:      return g_bufB;
        case BUF_CONCAT: return g_concat;
        case BUF_Y1:     return g_y1;
        case BUF_Y2:     return g_y2;
        default:         return nullptr;
    }
}

// ------------------------- packed f32x2 helpers ----------------------------
__device__ __forceinline__ ull pack2(float x, float y) {
    ull r; asm("mov.b64 %0, {%1, %2};" : "=l"(r) : "f"(x), "f"(y)); return r;
}
__device__ __forceinline__ void fma2(ull& d, ull a, ull b) {
    asm("fma.rn.f32x2 %0, %1, %2, %0;" : "+l"(d) : "l"(a), "l"(b));
}
__device__ __forceinline__ float2 unpack2(ull v) {
    float2 f; asm("mov.b64 {%0, %1}, %2;" : "=f"(f.x), "=f"(f.y) : "l"(v)); return f;
}

// ------------------------- BN folding --------------------------------------
__global__ void bn_prep_kernel(const float* __restrict__ g, const float* __restrict__ be,
                               const float* __restrict__ m, const float* __restrict__ v,
                               const float* __restrict__ cb, int off, int C) {
    int i = blockIdx.x * blockDim.x + threadIdx.x;
    if (i < C) {
        float s = g[i] / sqrtf(v[i] + 1e-5f);
        g_scale[off + i] = s;
        g_bias[off + i]  = (cb[i] - m[i]) * s + be[i];
    }
}

// ------------------------- fused conv + BN + ReLU (FFMA2) ------------------
// Block: TW x TH threads. Tile: TH x (TW*SPT) outputs, OCB output channels.
// Output channels paired (2 per 64-bit accumulator lane pair).
// grid.z = NB * (OC/OCB). If MERGED, batch index b in [0,64):
//   input from ext0 (b<32) or ext1 (b>=32) when INBUF==BUF_EXT,
//   output to g_f0 (b<32) or g_f1 (b>=32) when OUTBUF==BUF_F0.
template <int IC, int OC, int K, int S, int P,
          int TH, int TW, int SPT, int OCB, int ICCH,
          int INBUF, int OUTBUF, bool MERGED>
__global__ void __launch_bounds__(TH * TW)
conv2_kernel(const float* __restrict__ ext0, const float* __restrict__ ext1,
             const float* __restrict__ W, int bn_off,
             int IH, int IW, int OH, int OW) {
    constexpr int IN_TH = (TH - 1) * S + K;
    constexpr int IN_TW = (TW * SPT - 1) * S + K;
    constexpr int OCP   = OCB / 2;

    __shared__ float sIn[ICCH][IN_TH][IN_TW];
    __shared__ __align__(8) float sW[ICCH][K][K][OCB];   // oc fastest -> LDS.64 pairs

    const int tx = threadIdx.x, ty = threadIdx.y;
    const int tid = ty * TW + tx;
    const int nthreads = TH * TW;

    const int nOcb = OC / OCB;
    const int b    = blockIdx.z / nOcb;
    const int ocb0 = (blockIdx.z % nOcb) * OCB;
    const int oh0  = blockIdx.y * TH;
    const int ow0  = blockIdx.x * (TW * SPT);
    const int in_r0 = oh0 * S - P;
    const int in_c0 = ow0 * S - P;

    const float* inb;
    if (INBUF == BUF_EXT)
        inb = (MERGED && b >= 32 ? ext1 : ext0) + (size_t)(b & 31) * IC * IH * IW;
    else
        inb = get_buf(INBUF) + (size_t)b * IC * IH * IW;

    float* out; int bo = b;
    if (OUTBUF == BUF_F0) { out = (b < 32) ? g_f0 : g_f1; bo = b & 31; }
    else                  { out = get_buf(OUTBUF); }

    ull acc[SPT][OCP];
#pragma unroll
    for (int sp = 0; sp < SPT; sp++)
#pragma unroll
        for (int o = 0; o < OCP; o++) acc[sp][o] = 0ull;

    for (int ic0 = 0; ic0 < IC; ic0 += ICCH) {
        // --- load input tile ---
        for (int i = tid; i < ICCH * IN_TH * IN_TW; i += nthreads) {
            int c   = i / (IN_TH * IN_TW);
            int rem = i % (IN_TH * IN_TW);
            int r   = rem / IN_TW;
            int cc  = rem % IN_TW;
            int gch = ic0 + c;
            int gr  = in_r0 + r;
            int gc  = in_c0 + cc;
            float v = 0.f;
            if (gch < IC && gr >= 0 && gr < IH && gc >= 0 && gc < IW)
                v = inb[((size_t)gch * IH + gr) * IW + gc];
            (&sIn[0][0][0])[i] = v;
        }
        // --- load weight chunk (oc fastest for packed pairs) ---
        for (int i = tid; i < ICCH * K * K * OCB; i += nthreads) {
            int c   = i / (K * K * OCB);
            int rem = i % (K * K * OCB);
            int kk  = rem / OCB;
            int o   = rem % OCB;
            int gch = ic0 + c;
            float v = 0.f;
            if (gch < IC)
                v = W[((size_t)(ocb0 + o) * IC + gch) * (K * K) + kk];
            (&sW[0][0][0][0])[i] = v;
        }
        __syncthreads();

        // --- accumulate (packed f32x2) ---
#pragma unroll
        for (int c = 0; c < ICCH; c++) {
#pragma unroll
            for (int ky = 0; ky < K; ky++) {
#pragma unroll
                for (int kx = 0; kx < K; kx++) {
                    ull ivp[SPT];
#pragma unroll
                    for (int sp = 0; sp < SPT; sp++) {
                        float iv = sIn[c][ty * S + ky][(sp * TW + tx) * S + kx];
                        ivp[sp] = pack2(iv, iv);
                    }
                    const ull* wp = reinterpret_cast<const ull*>(&sW[c][ky][kx][0]);
#pragma unroll
                    for (int o = 0; o < OCP; o++) {
                        ull wv = wp[o];
#pragma unroll
                        for (int sp = 0; sp < SPT; sp++)
                            fma2(acc[sp][o], ivp[sp], wv);
                    }
                }
            }
        }
        __syncthreads();
    }

    // --- epilogue: BN + ReLU + store ---
    const int oh = oh0 + ty;
#pragma unroll
    for (int o = 0; o < OCP; o++) {
        int oc0 = ocb0 + 2 * o;
        float s0 = g_scale[bn_off + oc0],     t0 = g_bias[bn_off + oc0];
        float s1 = g_scale[bn_off + oc0 + 1], t1 = g_bias[bn_off + oc0 + 1];
#pragma unroll
        for (int sp = 0; sp < SPT; sp++) {
            int ow = ow0 + sp * TW + tx;
            float2 v = unpack2(acc[sp][o]);
            float r0 = fmaxf(fmaf(v.x, s0, t0), 0.f);
            float r1 = fmaxf(fmaf(v.y, s1, t1), 0.f);
            out[(((size_t)bo * OC + oc0)     * OH + oh) * OW + ow] = r0;
            out[(((size_t)bo * OC + oc0 + 1) * OH + oh) * OW + ow] = r1;
        }
    }
}

// ------------------------- per-pixel inverse L2 norm -----------------------
__global__ void l2inv_kernel(int which) {
    const float* in = which ? g_f1 : g_f0;
    float* inv      = which ? g_inv1 : g_inv0;
    int idx = blockIdx.x * blockDim.x + threadIdx.x;
    const int HW = 48 * 64;
    if (idx >= BATCH * HW) return;
    int b  = idx / HW;
    int hw = idx % HW;
    const float* p = in + (size_t)b * 128 * HW + hw;
    float ss = 0.f;
#pragma unroll 8
    for (int c = 0; c < 128; c++) {
        float v = p[(size_t)c * HW];
        ss = fmaf(v, v, ss);
    }
    inv[idx] = 1.0f / fmaxf(sqrtf(ss), 1e-12f);
}

// ------------------------- correlation volume ------------------------------
// grid = (H=48, B=32), block = 64. Normalization fused via inverse norms.
__global__ void __launch_bounds__(64)
corr_kernel() {
    const int H = 48, W = 64, C = 128, HW = H * W;
    const int h = blockIdx.x;
    const int b = blockIdx.y;
    const int w = threadIdx.x;

    __shared__ float sF0[8][9][72];
    __shared__ float sF1[8][64];
    __shared__ float sInv0[9][72];
    __shared__ float sInv1[64];

    float acc[81];
#pragma unroll
    for (int o = 0; o < 81; o++) acc[o] = 0.f;

    const float* f0b = g_f0 + (size_t)b * C * HW;
    const float* f1b = g_f1 + (size_t)b * C * HW;
    const float* inv0b = g_inv0 + (size_t)b * HW;
    const float* inv1b = g_inv1 + (size_t)b * HW;

    sInv1[w] = inv1b[h * W + w];
    for (int i = w; i < 9 * 72; i += 64) {
        int r  = i / 72;
        int cc = i % 72;
        int gh = h + r - 4;
        int gw = cc - 4;
        float v = 0.f;
        if (gh >= 0 && gh < H && gw >= 0 && gw < W)
            v = inv0b[gh * W + gw];
        (&sInv0[0][0])[i] = v;
    }
    __syncthreads();

    for (int c0 = 0; c0 < C; c0 += 8) {
        for (int i = w; i < 8 * 64; i += 64) {
            int c = i >> 6, ww = i & 63;
            sF1[c][ww] = f1b[(size_t)(c0 + c) * HW + h * W + ww] * sInv1[ww];
        }
        for (int i = w; i < 8 * 9 * 72; i += 64) {
            int c   = i / (9 * 72);
            int rem = i % (9 * 72);
            int r   = rem / 72;
            int cc  = rem % 72;
            int gh = h + r - 4;
            int gw = cc - 4;
            float v = 0.f;
            if (gh >= 0 && gh < H && gw >= 0 && gw < W)
                v = f0b[(size_t)(c0 + c) * HW + gh * W + gw] * sInv0[r][cc];
            (&sF0[0][0][0])[i] = v;
        }
        __syncthreads();
#pragma unroll
        for (int c = 0; c < 8; c++) {
            float iv = sF1[c][w];
#pragma unroll
            for (int r = 0; r < 9; r++)
#pragma unroll
                for (int d = 0; d < 9; d++)
                    acc[r * 9 + d] = fmaf(sF0[c][r][w + d], iv, acc[r * 9 + d]);
        }
        __syncthreads();
    }
#pragma unroll
    for (int o = 0; o < 81; o++)
        g_concat[(((size_t)b * 209 + o) * H + h) * W + w] = acc[o];
}

// ------------------------- copy raw f1 into concat[:, 81:209] --------------
__global__ void copy_f1_kernel() {
    const int HW = 48 * 64;
    size_t i = (size_t)blockIdx.x * blockDim.x + threadIdx.x;
    size_t total = (size_t)BATCH * 128 * HW;
    if (i >= total) return;
    int b   = (int)(i / (128 * HW));
    int rem = (int)(i % (128 * HW));
    g_concat[(size_t)b * 209 * HW + (size_t)81 * HW + rem] = g_f1[i];
}

// ------------------------- global average pool -----------------------------
__global__ void __launch_bounds__(128)
avgpool_kernel(float* __restrict__ out) {
    __shared__ float sred[4];
    int bo = blockIdx.x;
    const float* p = g_y2 + (size_t)bo * 768;
    float s = 0.f;
    for (int i = threadIdx.x; i < 768; i += 128) s += p[i];
#pragma unroll
    for (int o = 16; o > 0; o >>= 1) s += __shfl_down_sync(0xFFFFFFFFu, s, o);
    if ((threadIdx.x & 31) == 0) sred[threadIdx.x >> 5] = s;
    __syncthreads();
    if (threadIdx.x == 0) {
        float t = sred[0] + sred[1] + sred[2] + sred[3];
        out[bo] = t * (1.0f / 768.0f);
    }
}

// ---------------------------------------------------------------------------
extern "C" void kernel_launch(void* const* d_in, const int* in_sizes, int n_in,
                              void* d_out, int out_size) {
    (void)in_sizes; (void)n_in; (void)out_size;

    const float* img0 = (const float*)d_in[0];
    const float* img1 = (const float*)d_in[1];
    const float* w1 = (const float*)d_in[2];  const float* b1 = (const float*)d_in[3];
    const float* g1 = (const float*)d_in[4];  const float* be1 = (const float*)d_in[5];
    const float* m1 = (const float*)d_in[6];  const float* v1 = (const float*)d_in[7];
    const float* w2 = (const float*)d_in[8];  const float* b2 = (const float*)d_in[9];
    const float* g2 = (const float*)d_in[10]; const float* be2 = (const float*)d_in[11];
    const float* m2 = (const float*)d_in[12]; const float* v2 = (const float*)d_in[13];
    const float* w3 = (const float*)d_in[14]; const float* b3 = (const float*)d_in[15];
    const float* g3 = (const float*)d_in[16]; const float* be3 = (const float*)d_in[17];
    const float* m3 = (const float*)d_in[18]; const float* v3 = (const float*)d_in[19];
    const float* wf1 = (const float*)d_in[20]; const float* bf1 = (const float*)d_in[21];
    const float* gf1 = (const float*)d_in[22]; const float* bef1 = (const float*)d_in[23];
    const float* mf1 = (const float*)d_in[24]; const float* vf1 = (const float*)d_in[25];
    const float* wf2 = (const float*)d_in[26]; const float* bf2 = (const float*)d_in[27];
    const float* gf2 = (const float*)d_in[28]; const float* bef2 = (const float*)d_in[29];
    const float* mf2 = (const float*)d_in[30]; const float* vf2 = (const float*)d_in[31];

    // --- fold BN params ---
    bn_prep_kernel<<<1, 256>>>(g1, be1, m1, v1, b1, 0, 32);
    bn_prep_kernel<<<1, 256>>>(g2, be2, m2, v2, b2, 32, 64);
    bn_prep_kernel<<<1, 256>>>(g3, be3, m3, v3, b3, 96, 128);
    bn_prep_kernel<<<1, 256>>>(gf1, bef1, mf1, vf1, bf1, 224, 256);
    bn_prep_kernel<<<1, 256>>>(gf2, bef2, mf2, vf2, bf2, 480, 256);

    dim3 blk(16, 8);

    // --- backbone, merged batch of 64 (img0 ++ img1) ---
    conv2_kernel<3, 32, 7, 2, 3, 8, 16, 4, 16, 3, BUF_EXT, BUF_A, true>
        <<<dim3(4, 24, 64 * 2), blk>>>(img0, img1, w1, 0, 384, 512, 192, 256);
    conv2_kernel<32, 64, 5, 2, 2, 8, 16, 4, 16, 4, BUF_A, BUF_B, true>
        <<<dim3(2, 12, 64 * 4), blk>>>(nullptr, nullptr, w2, 32, 192, 256, 96, 128);
    conv2_kernel<64, 128, 3, 2, 1, 8, 16, 4, 16, 4, BUF_B, BUF_F0, true>
        <<<dim3(1, 6, 64 * 8), blk>>>(nullptr, nullptr, w3, 96, 96, 128, 48, 64);

    // --- inverse L2 norms ---
    {
        int n = BATCH * 48 * 64;
        l2inv_kernel<<<(n + 127) / 128, 128>>>(0);
        l2inv_kernel<<<(n + 127) / 128, 128>>>(1);
    }

    // --- correlation + f1 copy into concat ---
    corr_kernel<<<dim3(48, BATCH), 64>>>();
    {
        size_t n = (size_t)BATCH * 128 * 48 * 64;
        copy_f1_kernel<<<(unsigned)((n + 255) / 256), 256>>>();
    }

    // --- fusion convs ---
    conv2_kernel<209, 256, 3, 2, 1, 8, 16, 2, 16, 8, BUF_CONCAT, BUF_Y1, false>
        <<<dim3(1, 3, BATCH * 16), blk>>>(nullptr, nullptr, wf1, 224, 48, 64, 24, 32);
    conv2_kernel<256, 256, 3, 1, 1, 8, 16, 2, 16, 8, BUF_Y1, BUF_Y2, false>
        <<<dim3(1, 3, BATCH * 16), blk>>>(nullptr, nullptr, wf2, 480, 24, 32, 24, 32);

    // --- global average pool -> (B,256) ---
    avgpool_kernel<<<BATCH * 256, 128>>>((float*)d_out);
}

// round 6
// speedup vs baseline: 3.1998x; 2.3443x over previous
#include <cuda_runtime.h>
#include <math.h>

typedef unsigned int uint32;

#define BATCH 32

// ---------------------------------------------------------------------------
// FlowEncoder — tf32 tensor-core implicit GEMM (mma.sync.m16n8k8), NHWC.
//   conv1 7x7 s2 p3  : [64]x384x512x8(pad3) -> [64]x192x256x32
//   conv2 5x5 s2 p2  : -> [64]x96x128x64
//   conv3 3x3 s2 p1  : -> [64]x48x64x128   (feat; b<32 = f0, b>=32 = f1)
//   corr d=4 (l2norm fused) + concat      -> [32]x48x64x216 (209 + pad)
//   convf1 3x3 s2 p1 : -> [32]x24x32x256
//   convf2 3x3 s1 p1 : -> [32]x24x32x256
//   avgpool -> (32,256)
// BN folded: scale into weights (at transform time), bias in epilogue.
// ---------------------------------------------------------------------------

// ------------------------- device scratch (no allocs) ----------------------
__device__ __align__(16) float g_act1[(size_t)64 * 192 * 256 * 32];
__device__ __align__(16) float g_act2[(size_t)64 * 96 * 128 * 64];
__device__ __align__(16) float g_feat[(size_t)64 * 48 * 64 * 128];
__device__ __align__(16) float g_concat[(size_t)32 * 48 * 64 * 216];
__device__ __align__(16) float g_y1[(size_t)32 * 24 * 32 * 256];
__device__ __align__(16) float g_y2[(size_t)32 * 24 * 32 * 256];
__device__ float g_inv[(size_t)64 * 48 * 64];
__device__ __align__(16) uint32 g_wt[1224960];   // transformed tf32 weights
__device__ float g_scale[736];
__device__ float g_bias[736];

enum { BUF_EXT = 0, BUF_ACT1, BUF_ACT2, BUF_FEAT, BUF_CONCAT, BUF_Y1, BUF_Y2 };

__device__ __forceinline__ float* get_buf(int id) {
    switch (id) {
        case BUF_ACT1:   return g_act1;
        case BUF_ACT2:   return g_act2;
        case BUF_FEAT:   return g_feat;
        case BUF_CONCAT: return g_concat;
        case BUF_Y1:     return g_y1;
        case BUF_Y2:     return g_y2;
        default:         return nullptr;
    }
}

// ------------------------- helpers -----------------------------------------
__device__ __forceinline__ uint32 to_tf32(float f) {
    uint32 u; asm("cvt.rna.tf32.f32 %0, %1;" : "=r"(u) : "f"(f)); return u;
}
__device__ __forceinline__ void mma_tf32(float* d, uint32 a0, uint32 a1, uint32 a2, uint32 a3,
                                         uint32 b0, uint32 b1) {
    asm volatile(
        "mma.sync.aligned.m16n8k8.row.col.f32.tf32.tf32.f32 "
        "{%0,%1,%2,%3},{%4,%5,%6,%7},{%8,%9},{%0,%1,%2,%3};"
        : "+f"(d[0]), "+f"(d[1]), "+f"(d[2]), "+f"(d[3])
        : "r"(a0), "r"(a1), "r"(a2), "r"(a3), "r"(b0), "r"(b1));
}

// ------------------------- BN folding --------------------------------------
__global__ void bn_prep_kernel(const float* __restrict__ g, const float* __restrict__ be,
                               const float* __restrict__ m, const float* __restrict__ v,
                               const float* __restrict__ cb, int off, int C) {
    int i = blockIdx.x * blockDim.x + threadIdx.x;
    if (i < C) {
        float s = g[i] / sqrtf(v[i] + 1e-5f);
        g_scale[off + i] = s;
        g_bias[off + i]  = (cb[i] - m[i]) * s + be[i];
    }
}

// ------------------------- weight transform --------------------------------
// dst layout: [nb][chunk][tap][j][k][n8], tf32 bits, pre-scaled by BN scale.
__global__ void wt_prep_kernel(const float* __restrict__ W,
                               int ICR, int NT, int KK,
                               int NTILES, int NCHUNK,
                               int wt_off, int bn_off, int total) {
    int i = blockIdx.x * blockDim.x + threadIdx.x;
    if (i >= total) return;
    int n8    = i & 7;
    int k     = (i >> 3) & 7;
    int j     = (i >> 6) % NTILES;
    int tap   = (i / (64 * NTILES)) % KK;
    int chunk = (i / (64 * NTILES * KK)) % NCHUNK;
    int nb    = i / (64 * NTILES * KK * NCHUNK);
    int oc = nb * NT + j * 8 + n8;
    int ic = chunk * 8 + k;
    float val = 0.f;
    if (ic < ICR)
        val = W[((size_t)oc * ICR + ic) * KK + tap] * g_scale[bn_off + oc];
    g_wt[wt_off + i] = to_tf32(val);
}

// ------------------------- conv (tf32 mma implicit GEMM) -------------------
// 512 threads = 16 warps. Block computes 256 spatial (TOH x TOW) x NT oc.
// Warp w owns spatial rows m = [w*16, w*16+16).
template <int ICP, int ICR, int OC, int NT, int K, int S, int P,
          int TOH, int TOW, int IH, int IW, int OH, int OW,
          int INBUF, int OUTBUF>
__global__ void __launch_bounds__(512)
conv_mma(const float* __restrict__ ext0, const float* __restrict__ ext1,
         int wt_off, int bn_off) {
    constexpr int INTH   = (TOH - 1) * S + K;
    constexpr int INTW   = (TOW - 1) * S + K;
    constexpr int NTILES = NT / 8;
    constexpr int NCHUNK = ICP / 8;
    constexpr int NOCB   = OC / NT;
    constexpr int SIN_SZ  = INTH * INTW * 10;          // pixel stride 10 (bank pad)
    constexpr int SIN_PAD = (SIN_SZ + 3) & ~3;         // 16B-align the weight region
    constexpr int SW_SZ   = K * K * NT * 8;

    extern __shared__ __align__(16) uint32 smem[];
    uint32* sIn = smem;
    uint32* sW  = smem + SIN_PAD;

    const int tid  = threadIdx.x;
    const int lane = tid & 31;
    const int wid  = tid >> 5;

    const int b   = blockIdx.z / NOCB;
    const int nb  = blockIdx.z % NOCB;
    const int oc0 = nb * NT;
    const int oh0 = blockIdx.y * TOH;
    const int ow0 = blockIdx.x * TOW;
    const int ir0 = oh0 * S - P;
    const int ic0 = ow0 * S - P;

    const float* in_nchw = nullptr;   // conv1 path
    const float* in_nhwc = nullptr;
    if (INBUF == BUF_EXT)
        in_nchw = (b < 32 ? ext0 : ext1) + (size_t)(b & 31) * 3 * IH * IW;
    else
        in_nhwc = get_buf(INBUF) + (size_t)b * IH * IW * ICP;

    const uint32* wt = g_wt + wt_off + (size_t)nb * NCHUNK * SW_SZ;

    float acc[NTILES][4];
#pragma unroll
    for (int j = 0; j < NTILES; j++)
#pragma unroll
        for (int q = 0; q < 4; q++) acc[j][q] = 0.f;

    // per-lane fragment bases
    const int p0 = wid * 16 + (lane >> 2);
    const int p1 = p0 + 8;
    const int a0base = (((p0 / TOW) * S) * INTW + (p0 % TOW) * S) * 10 + (lane & 3);
    const int a1base = (((p1 / TOW) * S) * INTW + (p1 % TOW) * S) * 10 + (lane & 3);
    const int bbase  = (lane & 3) * 8 + (lane >> 2);

    for (int chunk = 0; chunk < NCHUNK; chunk++) {
        const int c0 = chunk * 8;
        // ---- stage input tile (tf32 in smem) ----
        if (INBUF == BUF_EXT) {
            for (int i = tid; i < INTH * INTW * 8; i += 512) {
                int c   = i & 7;
                int pix = i >> 3;
                int r   = pix / INTW;
                int cc  = pix % INTW;
                int gr  = ir0 + r;
                int gc  = ic0 + cc;
                float v = 0.f;
                if (c < ICR && gr >= 0 && gr < IH && gc >= 0 && gc < IW)
                    v = in_nchw[(size_t)c * IH * IW + (size_t)gr * IW + gc];
                sIn[pix * 10 + c] = to_tf32(v);
            }
        } else {
            for (int i = tid; i < INTH * INTW * 4; i += 512) {
                int c2  = (i & 3) * 2;
                int pix = i >> 2;
                int r   = pix / INTW;
                int cc  = pix % INTW;
                int gr  = ir0 + r;
                int gc  = ic0 + cc;
                float2 v = make_float2(0.f, 0.f);
                if (gr >= 0 && gr < IH && gc >= 0 && gc < IW)
                    v = *(const float2*)&in_nhwc[((size_t)gr * IW + gc) * ICP + c0 + c2];
                sIn[pix * 10 + c2]     = to_tf32(v.x);
                sIn[pix * 10 + c2 + 1] = to_tf32(v.y);
            }
        }
        // ---- stage weight chunk (already transformed) ----
        {
            const uint4* src = (const uint4*)(wt + (size_t)chunk * SW_SZ);
            uint4* dst = (uint4*)sW;
            for (int i = tid; i < SW_SZ / 4; i += 512) dst[i] = src[i];
        }
        __syncthreads();

        // ---- mma over taps ----
#pragma unroll
        for (int ky = 0; ky < K; ky++) {
#pragma unroll
            for (int kx = 0; kx < K; kx++) {
                const int aoff = (ky * INTW + kx) * 10;
                uint32 A0 = sIn[a0base + aoff];
                uint32 A1 = sIn[a1base + aoff];
                uint32 A2 = sIn[a0base + aoff + 4];
                uint32 A3 = sIn[a1base + aoff + 4];
                const int tapoff = (ky * K + kx) * NT * 8;
#pragma unroll
                for (int j = 0; j < NTILES; j++) {
                    uint32 B0 = sW[tapoff + j * 64 + bbase];
                    uint32 B1 = sW[tapoff + j * 64 + bbase + 32];
                    mma_tf32(acc[j], A0, A1, A2, A3, B0, B1);
                }
            }
        }
        __syncthreads();
    }

    // ---- epilogue: +bias, ReLU, NHWC store ----
    float* outp = get_buf(OUTBUF) + (size_t)b * OH * OW * OC;
    const int goh0 = oh0 + p0 / TOW, gow0 = ow0 + p0 % TOW;
    const int goh1 = oh0 + p1 / TOW, gow1 = ow0 + p1 % TOW;
#pragma unroll
    for (int j = 0; j < NTILES; j++) {
        int oc = oc0 + j * 8 + (lane & 3) * 2;
        float bi0 = g_bias[bn_off + oc];
        float bi1 = g_bias[bn_off + oc + 1];
        float2 r0 = make_float2(fmaxf(acc[j][0] + bi0, 0.f), fmaxf(acc[j][1] + bi1, 0.f));
        float2 r1 = make_float2(fmaxf(acc[j][2] + bi0, 0.f), fmaxf(acc[j][3] + bi1, 0.f));
        *(float2*)&outp[((size_t)goh0 * OW + gow0) * OC + oc] = r0;
        *(float2*)&outp[((size_t)goh1 * OW + gow1) * OC + oc] = r1;
    }
}

// ------------------------- per-pixel inverse L2 norm (NHWC feat) -----------
__global__ void __launch_bounds__(256) l2inv_kernel() {
    int pix  = blockIdx.x * 8 + (threadIdx.x >> 5);
    int lane = threadIdx.x & 31;
    float4 v = *(const float4*)&g_feat[(size_t)pix * 128 + lane * 4];
    float ss = v.x * v.x + v.y * v.y + v.z * v.z + v.w * v.w;
#pragma unroll
    for (int o = 16; o > 0; o >>= 1) ss += __shfl_xor_sync(0xFFFFFFFFu, ss, o);
    if (lane == 0) g_inv[pix] = 1.0f / fmaxf(sqrtf(ss), 1e-12f);
}

// ------------------------- correlation volume (NHWC) -----------------------
// grid (48, 32), block 64. Writes concat channels [0,81).
__global__ void __launch_bounds__(64)
corr_kernel() {
    const int H = 48, W = 64;
    const int h = blockIdx.x;
    const int b = blockIdx.y;
    const int w = threadIdx.x;

    __shared__ float sF0[8][9][72];
    __shared__ float sF1[8][64];
    __shared__ float sInv0[9][72];
    __shared__ float sInv1[64];

    float acc[81];
#pragma unroll
    for (int o = 0; o < 81; o++) acc[o] = 0.f;

    const float* f0b = g_feat + (size_t)b * H * W * 128;
    const float* f1b = g_feat + (size_t)(b + 32) * H * W * 128;

    sInv1[w] = g_inv[((size_t)(b + 32) * H + h) * W + w];
    for (int i = w; i < 9 * 72; i += 64) {
        int r  = i / 72;
        int cc = i % 72;
        int gh = h + r - 4;
        int gw = cc - 4;
        float v = 0.f;
        if (gh >= 0 && gh < H && gw >= 0 && gw < W)
            v = g_inv[((size_t)b * H + gh) * W + gw];
        (&sInv0[0][0])[i] = v;
    }
    __syncthreads();

    for (int c0 = 0; c0 < 128; c0 += 8) {
        for (int i = w; i < 8 * 64; i += 64) {
            int c = i >> 6, ww = i & 63;
            sF1[c][ww] = f1b[((size_t)h * W + ww) * 128 + c0 + c] * sInv1[ww];
        }
        for (int i = w; i < 8 * 9 * 72; i += 64) {
            int c   = i / (9 * 72);
            int rem = i % (9 * 72);
            int r   = rem / 72;
            int cc  = rem % 72;
            int gh = h + r - 4;
            int gw = cc - 4;
            float v = 0.f;
            if (gh >= 0 && gh < H && gw >= 0 && gw < W)
                v = f0b[((size_t)gh * W + gw) * 128 + c0 + c] * sInv0[r][cc];
            (&sF0[0][0][0])[i] = v;
        }
        __syncthreads();
#pragma unroll
        for (int c = 0; c < 8; c++) {
            float iv = sF1[c][w];
#pragma unroll
            for (int r = 0; r < 9; r++)
#pragma unroll
                for (int d = 0; d < 9; d++)
                    acc[r * 9 + d] = fmaf(sF0[c][r][w + d], iv, acc[r * 9 + d]);
        }
        __syncthreads();
    }
    float* dst = g_concat + ((size_t)(b * H + h) * W + w) * 216;
#pragma unroll
    for (int o = 0; o < 81; o++) dst[o] = acc[o];
}

// ------------------------- f1 copy + pad into concat -----------------------
__global__ void copy_f1_kernel() {
    int pix = blockIdx.x * blockDim.x + threadIdx.x;      // over 32*48*64
    if (pix >= 32 * 48 * 64) return;
    const float* src = g_feat + ((size_t)pix + (size_t)32 * 48 * 64) * 128;
    float* dst = g_concat + (size_t)pix * 216;
    for (int c = 0; c < 128; c++) dst[81 + c] = src[c];
    for (int c = 209; c < 216; c++) dst[c] = 0.f;
}

// ------------------------- global average pool (NHWC) ----------------------
__global__ void __launch_bounds__(256)
avgpool_kernel(float* __restrict__ out) {
    int b = blockIdx.x;
    int c = threadIdx.x;
    const float* p = g_y2 + (size_t)b * 768 * 256 + c;
    float s = 0.f;
    for (int i = 0; i < 768; i++) s += p[(size_t)i * 256];
    out[b * 256 + c] = s * (1.0f / 768.0f);
}

// ---------------------------------------------------------------------------
extern "C" void kernel_launch(void* const* d_in, const int* in_sizes, int n_in,
                              void* d_out, int out_size) {
    (void)in_sizes; (void)n_in; (void)out_size;

    const float* img0 = (const float*)d_in[0];
    const float* img1 = (const float*)d_in[1];
    const float* w1 = (const float*)d_in[2];  const float* b1 = (const float*)d_in[3];
    const float* g1 = (const float*)d_in[4];  const float* be1 = (const float*)d_in[5];
    const float* m1 = (const float*)d_in[6];  const float* v1 = (const float*)d_in[7];
    const float* w2 = (const float*)d_in[8];  const float* b2 = (const float*)d_in[9];
    const float* g2 = (const float*)d_in[10]; const float* be2 = (const float*)d_in[11];
    const float* m2 = (const float*)d_in[12]; const float* v2 = (const float*)d_in[13];
    const float* w3 = (const float*)d_in[14]; const float* b3 = (const float*)d_in[15];
    const float* g3 = (const float*)d_in[16]; const float* be3 = (const float*)d_in[17];
    const float* m3 = (const float*)d_in[18]; const float* v3 = (const float*)d_in[19];
    const float* wf1 = (const float*)d_in[20]; const float* bf1 = (const float*)d_in[21];
    const float* gf1 = (const float*)d_in[22]; const float* bef1 = (const float*)d_in[23];
    const float* mf1 = (const float*)d_in[24]; const float* vf1 = (const float*)d_in[25];
    const float* wf2 = (const float*)d_in[26]; const float* bf2 = (const float*)d_in[27];
    const float* gf2 = (const float*)d_in[28]; const float* bef2 = (const float*)d_in[29];
    const float* mf2 = (const float*)d_in[30]; const float* vf2 = (const float*)d_in[31];

    // --- fold BN params (scale/bias) ---
    bn_prep_kernel<<<1, 256>>>(g1, be1, m1, v1, b1, 0, 32);
    bn_prep_kernel<<<1, 256>>>(g2, be2, m2, v2, b2, 32, 64);
    bn_prep_kernel<<<1, 256>>>(g3, be3, m3, v3, b3, 96, 128);
    bn_prep_kernel<<<1, 256>>>(gf1, bef1, mf1, vf1, bf1, 224, 256);
    bn_prep_kernel<<<1, 256>>>(gf2, bef2, mf2, vf2, bf2, 480, 256);

    // --- weight transforms (tf32 + scale fold) ---
    wt_prep_kernel<<<(12544 + 255) / 256, 256>>>(w1, 3, 32, 49, 4, 1, 0, 0, 12544);
    wt_prep_kernel<<<(51200 + 255) / 256, 256>>>(w2, 32, 64, 25, 8, 4, 12544, 32, 51200);
    wt_prep_kernel<<<(73728 + 255) / 256, 256>>>(w3, 64, 64, 9, 8, 8, 63744, 96, 73728);
    wt_prep_kernel<<<(497664 + 255) / 256, 256>>>(wf1, 209, 64, 9, 8, 27, 137472, 224, 497664);
    wt_prep_kernel<<<(589824 + 255) / 256, 256>>>(wf2, 256, 64, 9, 8, 32, 635136, 480, 589824);

    // --- conv1: 7x7 s2, NCHW imgs (merged 64) -> act1 ---
    {
        auto k = conv_mma<8, 3, 32, 32, 7, 2, 3, 16, 16, 384, 512, 192, 256, BUF_EXT, BUF_ACT1>;
        int sm = (((37 * 37 * 10 + 3) & ~3) + 49 * 32 * 8) * 4;
        cudaFuncSetAttribute(k, cudaFuncAttributeMaxDynamicSharedMemorySize, sm);
        k<<<dim3(16, 12, 64), 512, sm>>>(img0, img1, 0, 0);
    }
    // --- conv2: 5x5 s2 -> act2 ---
    {
        auto k = conv_mma<32, 32, 64, 64, 5, 2, 2, 16, 16, 192, 256, 96, 128, BUF_ACT1, BUF_ACT2>;
        int sm = (((35 * 35 * 10 + 3) & ~3) + 25 * 64 * 8) * 4;
        cudaFuncSetAttribute(k, cudaFuncAttributeMaxDynamicSharedMemorySize, sm);
        k<<<dim3(8, 6, 64), 512, sm>>>(nullptr, nullptr, 12544, 32);
    }
    // --- conv3: 3x3 s2 -> feat ---
    {
        auto k = conv_mma<64, 64, 128, 64, 3, 2, 1, 8, 32, 96, 128, 48, 64, BUF_ACT2, BUF_FEAT>;
        int sm = (((17 * 65 * 10 + 3) & ~3) + 9 * 64 * 8) * 4;
        cudaFuncSetAttribute(k, cudaFuncAttributeMaxDynamicSharedMemorySize, sm);
        k<<<dim3(2, 6, 128), 512, sm>>>(nullptr, nullptr, 63744, 96);
    }

    // --- inverse L2 norms (all 64 feature maps) ---
    l2inv_kernel<<<(64 * 48 * 64) / 8, 256>>>();

    // --- correlation + f1 copy into concat ---
    corr_kernel<<<dim3(48, 32), 64>>>();
    copy_f1_kernel<<<(32 * 48 * 64) / 256, 256>>>();

    // --- convf1: 3x3 s2 -> y1 ---
    {
        auto k = conv_mma<216, 209, 256, 64, 3, 2, 1, 8, 32, 48, 64, 24, 32, BUF_CONCAT, BUF_Y1>;
        int sm = (((17 * 65 * 10 + 3) & ~3) + 9 * 64 * 8) * 4;
        cudaFuncSetAttribute(k, cudaFuncAttributeMaxDynamicSharedMemorySize, sm);
        k<<<dim3(1, 3, 128), 512, sm>>>(nullptr, nullptr, 137472, 224);
    }
    // --- convf2: 3x3 s1 -> y2 ---
    {
        auto k = conv_mma<256, 256, 256, 64, 3, 1, 1, 8, 32, 24, 32, 24, 32, BUF_Y1, BUF_Y2>;
        int sm = (((10 * 34 * 10 + 3) & ~3) + 9 * 64 * 8) * 4;
        cudaFuncSetAttribute(k, cudaFuncAttributeMaxDynamicSharedMemorySize, sm);
        k<<<dim3(1, 3, 128), 512, sm>>>(nullptr, nullptr, 635136, 480);
    }

    // --- global average pool -> (32,256) ---
    avgpool_kernel<<<32, 256>>>((float*)d_out);
}

// round 8
// speedup vs baseline: 3.8440x; 1.2013x over previous
#include <cuda_runtime.h>
#include <math.h>

typedef unsigned int uint32;

#define BATCH 32

// ---------------------------------------------------------------------------
// FlowEncoder — tf32 tensor-core implicit GEMM, cp.async double-buffered.
// NHWC activations stored pre-rounded to tf32; conv hot loop has zero converts.
// ---------------------------------------------------------------------------

// ------------------------- device scratch (no allocs) ----------------------
__device__ __align__(16) float g_act1[(size_t)64 * 192 * 256 * 32];
__device__ __align__(16) float g_act2[(size_t)64 * 96 * 128 * 64];
__device__ __align__(16) float g_feat[(size_t)64 * 48 * 64 * 128];
__device__ __align__(16) float g_concat[(size_t)32 * 48 * 64 * 216];
__device__ __align__(16) float g_y1[(size_t)32 * 24 * 32 * 256];
__device__ __align__(16) float g_y2[(size_t)32 * 24 * 32 * 256];
__device__ float g_inv[(size_t)64 * 48 * 64];
__device__ __align__(16) uint32 g_wt[1224960];   // transformed tf32 weights
__device__ float g_scale[736];
__device__ float g_bias[736];

enum { BUF_EXT = 0, BUF_ACT1, BUF_ACT2, BUF_FEAT, BUF_CONCAT, BUF_Y1, BUF_Y2 };

__device__ __forceinline__ float* get_buf(int id) {
    switch (id) {
        case BUF_ACT1:   return g_act1;
        case BUF_ACT2:   return g_act2;
        case BUF_FEAT:   return g_feat;
        case BUF_CONCAT: return g_concat;
        case BUF_Y1:     return g_y1;
        case BUF_Y2:     return g_y2;
        default:         return nullptr;
    }
}

// ------------------------- helpers -----------------------------------------
__device__ __forceinline__ uint32 to_tf32(float f) {
    uint32 u; asm("cvt.rna.tf32.f32 %0, %1;" : "=r"(u) : "f"(f)); return u;
}
__device__ __forceinline__ float round_tf32(float f) {
    return __uint_as_float(to_tf32(f));
}
__device__ __forceinline__ void mma_tf32(float* d, uint32 a0, uint32 a1, uint32 a2, uint32 a3,
                                         uint32 b0, uint32 b1) {
    asm volatile(
        "mma.sync.aligned.m16n8k8.row.col.f32.tf32.tf32.f32 "
        "{%0,%1,%2,%3},{%4,%5,%6,%7},{%8,%9},{%0,%1,%2,%3};"
        : "+f"(d[0]), "+f"(d[1]), "+f"(d[2]), "+f"(d[3])
        : "r"(a0), "r"(a1), "r"(a2), "r"(a3), "r"(b0), "r"(b1));
}
__device__ __forceinline__ void cp_async8(uint32 dst, const void* src) {
    asm volatile("cp.async.ca.shared.global [%0], [%1], 8;" :: "r"(dst), "l"(src));
}
__device__ __forceinline__ void cp_async16(uint32 dst, const void* src) {
    asm volatile("cp.async.ca.shared.global [%0], [%1], 16;" :: "r"(dst), "l"(src));
}
__device__ __forceinline__ void cp_commit() { asm volatile("cp.async.commit_group;"); }
__device__ __forceinline__ void cp_wait0()  { asm volatile("cp.async.wait_group 0;"); }
__device__ __forceinline__ void cp_wait1()  { asm volatile("cp.async.wait_group 1;"); }

// ------------------------- BN folding --------------------------------------
__global__ void bn_prep_kernel(const float* __restrict__ g, const float* __restrict__ be,
                               const float* __restrict__ m, const float* __restrict__ v,
                               const float* __restrict__ cb, int off, int C) {
    int i = blockIdx.x * blockDim.x + threadIdx.x;
    if (i < C) {
        float s = g[i] / sqrtf(v[i] + 1e-5f);
        g_scale[off + i] = s;
        g_bias[off + i]  = (cb[i] - m[i]) * s + be[i];
    }
}

// ------------------------- weight transform --------------------------------
// dst layout: [nb][chunk][tap][j][k][n8], tf32 bits, pre-scaled by BN scale.
__global__ void wt_prep_kernel(const float* __restrict__ W,
                               int ICR, int NT, int KK,
                               int NTILES, int NCHUNK,
                               int wt_off, int bn_off, int total) {
    int i = blockIdx.x * blockDim.x + threadIdx.x;
    if (i >= total) return;
    int n8    = i & 7;
    int k     = (i >> 3) & 7;
    int j     = (i >> 6) % NTILES;
    int tap   = (i / (64 * NTILES)) % KK;
    int chunk = (i / (64 * NTILES * KK)) % NCHUNK;
    int nb    = i / (64 * NTILES * KK * NCHUNK);
    int oc = nb * NT + j * 8 + n8;
    int ic = chunk * 8 + k;
    float val = 0.f;
    if (ic < ICR)
        val = W[((size_t)oc * ICR + ic) * KK + tap] * g_scale[bn_off + oc];
    g_wt[wt_off + i] = to_tf32(val);
}

// ------------------------- conv (tf32 mma, cp.async pipeline) --------------
// 512 threads = 16 warps. Block computes 256 spatial (TOH x TOW) x NT oc.
template <int ICP, int ICR, int OC, int NT, int K, int S, int P,
          int TOH, int TOW, int IH, int IW, int OH, int OW,
          int INBUF, int OUTBUF, bool ROUND_OUT>
__global__ void __launch_bounds__(512)
conv_mma(const float* __restrict__ ext0, const float* __restrict__ ext1,
         int wt_off, int bn_off) {
    constexpr int INTH    = (TOH - 1) * S + K;
    constexpr int INTW    = (TOW - 1) * S + K;
    constexpr int NPIX    = INTH * INTW;
    constexpr int NTILES  = NT / 8;
    constexpr int NCHUNK  = ICP / 8;
    constexpr int NOCB    = OC / NT;
    constexpr int SIN_PAD = (NPIX * 10 + 3) & ~3;    // pixel stride 10 words
    constexpr int SW_SZ   = K * K * NT * 8;
    constexpr bool PIPE   = (NCHUNK > 1);
    constexpr int NBUF    = PIPE ? 2 : 1;

    extern __shared__ __align__(16) uint32 smem[];
    const uint32 smem_b = (uint32)__cvta_generic_to_shared(smem);

    const int tid  = threadIdx.x;
    const int lane = tid & 31;
    const int wid  = tid >> 5;

    const int b   = blockIdx.z / NOCB;
    const int nb  = blockIdx.z % NOCB;
    const int oc0 = nb * NT;
    const int oh0 = blockIdx.y * TOH;
    const int ow0 = blockIdx.x * TOW;
    const int ir0 = oh0 * S - P;
    const int ic0 = ow0 * S - P;

    const float* in_nchw = nullptr;
    const float* in_nhwc = nullptr;
    if (INBUF == BUF_EXT)
        in_nchw = (b < 32 ? ext0 : ext1) + (size_t)(b & 31) * 3 * IH * IW;
    else
        in_nhwc = get_buf(INBUF) + (size_t)b * IH * IW * ICP;

    const uint32* wt = g_wt + wt_off + (size_t)nb * NCHUNK * SW_SZ;

    float acc[NTILES][4];
#pragma unroll
    for (int j = 0; j < NTILES; j++)
#pragma unroll
        for (int q = 0; q < 4; q++) acc[j][q] = 0.f;

    // fragment base addresses (word indices within a buffer)
    const int p0 = wid * 16 + (lane >> 2);
    const int p1 = p0 + 8;
    const int a0base = (((p0 / TOW) * S) * INTW + (p0 % TOW) * S) * 10 + (lane & 3);
    const int a1base = (((p1 / TOW) * S) * INTW + (p1 % TOW) * S) * 10 + (lane & 3);
    const int bbase  = (lane & 3) * 8 + (lane >> 2);

    auto do_mma = [&](const uint32* sInb, const uint32* sWb) {
#pragma unroll
        for (int ky = 0; ky < K; ky++) {
#pragma unroll
            for (int kx = 0; kx < K; kx++) {
                const int aoff = (ky * INTW + kx) * 10;
                uint32 A0 = sInb[a0base + aoff];
                uint32 A1 = sInb[a1base + aoff];
                uint32 A2 = sInb[a0base + aoff + 4];
                uint32 A3 = sInb[a1base + aoff + 4];
                const int tapoff = (ky * K + kx) * NT * 8;
#pragma unroll
                for (int j = 0; j < NTILES; j++) {
                    uint32 B0 = sWb[tapoff + j * 64 + bbase];
                    uint32 B1 = sWb[tapoff + j * 64 + bbase + 32];
                    mma_tf32(acc[j], A0, A1, A2, A3, B0, B1);
                }
            }
        }
    };

    if (INBUF == BUF_EXT) {
        // ---- conv1: single chunk, synchronous staging, cvt at STS ----
        for (int i = tid; i < SIN_PAD; i += 512) smem[i] = 0;
        __syncthreads();
        for (int i = tid; i < NPIX * 3; i += 512) {
            int c = i / NPIX, pix = i % NPIX;          // pix fastest -> coalesced
            int r = pix / INTW, cc = pix % INTW;
            int gr = ir0 + r, gc = ic0 + cc;
            if (gr >= 0 && gr < IH && gc >= 0 && gc < IW)
                smem[pix * 10 + c] = to_tf32(in_nchw[(size_t)c * IH * IW + (size_t)gr * IW + gc]);
        }
        {
            uint32 d = smem_b + SIN_PAD * 4;
            for (int i = tid; i < SW_SZ / 4; i += 512)
                cp_async16(d + i * 16, wt + i * 4);
            cp_commit(); cp_wait0();
        }
        __syncthreads();
        do_mma(smem, smem + SIN_PAD);
    } else {
        // ---- pipelined path ----
        const int inO0 = 0, inO1 = SIN_PAD;
        const int wO0  = NBUF * SIN_PAD, wO1 = NBUF * SIN_PAD + SW_SZ;

        // pre-zero boundary pixels in both input buffers (disjoint from cp.async)
        for (int pix = tid; pix < NPIX; pix += 512) {
            int r = pix / INTW, cc = pix % INTW;
            int gr = ir0 + r, gc = ic0 + cc;
            if (!(gr >= 0 && gr < IH && gc >= 0 && gc < IW)) {
#pragma unroll
                for (int c = 0; c < 8; c++) {
                    smem[inO0 + pix * 10 + c] = 0;
                    smem[inO1 + pix * 10 + c] = 0;
                }
            }
        }

        auto stage_in = [&](int chunk, int off) {
            const float* base = in_nhwc + chunk * 8;
            for (int pix = tid; pix < NPIX; pix += 512) {
                int r = pix / INTW, cc = pix % INTW;
                int gr = ir0 + r, gc = ic0 + cc;
                if (gr >= 0 && gr < IH && gc >= 0 && gc < IW) {
                    const float* s = base + ((size_t)gr * IW + gc) * ICP;
                    uint32 d = smem_b + (off + pix * 10) * 4;
                    cp_async8(d,      s);
                    cp_async8(d + 8,  s + 2);
                    cp_async8(d + 16, s + 4);
                    cp_async8(d + 24, s + 6);
                }
            }
        };
        auto stage_w = [&](int chunk, int off) {
            const uint32* s = wt + (size_t)chunk * SW_SZ;
            uint32 d = smem_b + off * 4;
            for (int i = tid; i < SW_SZ / 4; i += 512)
                cp_async16(d + i * 16, s + i * 4);
        };

        stage_in(0, inO0); stage_w(0, wO0); cp_commit();
        for (int ch = 0; ch < NCHUNK; ch++) {
            if (ch + 1 < NCHUNK) {
                int nxt = (ch + 1) & 1;
                stage_in(ch + 1, nxt ? inO1 : inO0);
                stage_w(ch + 1, nxt ? wO1 : wO0);
                cp_commit();
                cp_wait1();
            } else {
                cp_wait0();
            }
            __syncthreads();
            int cur = ch & 1;
            do_mma(smem + (cur ? inO1 : inO0), smem + (cur ? wO1 : wO0));
            __syncthreads();
        }
    }

    // ---- epilogue: +bias, ReLU, optional tf32 round, NHWC store ----
    float* outp = get_buf(OUTBUF) + (size_t)b * OH * OW * OC;
    const int goh0 = oh0 + p0 / TOW, gow0 = ow0 + p0 % TOW;
    const int goh1 = oh0 + p1 / TOW, gow1 = ow0 + p1 % TOW;
#pragma unroll
    for (int j = 0; j < NTILES; j++) {
        int oc = oc0 + j * 8 + (lane & 3) * 2;
        float bi0 = g_bias[bn_off + oc];
        float bi1 = g_bias[bn_off + oc + 1];
        float v0 = fmaxf(acc[j][0] + bi0, 0.f);
        float v1 = fmaxf(acc[j][1] + bi1, 0.f);
        float v2 = fmaxf(acc[j][2] + bi0, 0.f);
        float v3 = fmaxf(acc[j][3] + bi1, 0.f);
        if (ROUND_OUT) {
            v0 = round_tf32(v0); v1 = round_tf32(v1);
            v2 = round_tf32(v2); v3 = round_tf32(v3);
        }
        *(float2*)&outp[((size_t)goh0 * OW + gow0) * OC + oc] = make_float2(v0, v1);
        *(float2*)&outp[((size_t)goh1 * OW + gow1) * OC + oc] = make_float2(v2, v3);
    }
}

// ------------------------- per-pixel inverse L2 norm (NHWC feat) -----------
__global__ void __launch_bounds__(256) l2inv_kernel() {
    int pix  = blockIdx.x * 8 + (threadIdx.x >> 5);
    int lane = threadIdx.x & 31;
    float4 v = *(const float4*)&g_feat[(size_t)pix * 128 + lane * 4];
    float ss = v.x * v.x + v.y * v.y + v.z * v.z + v.w * v.w;
#pragma unroll
    for (int o = 16; o > 0; o >>= 1) ss += __shfl_xor_sync(0xFFFFFFFFu, ss, o);
    if (lane == 0) g_inv[pix] = 1.0f / fmaxf(sqrtf(ss), 1e-12f);
}

// ------------------------- correlation volume (NHWC, coalesced) ------------
// grid (48, 32), block 64. Writes concat channels [0,81), tf32-rounded.
__global__ void __launch_bounds__(64)
corr_kernel() {
    const int H = 48, W = 64;
    const int h = blockIdx.x;
    const int b = blockIdx.y;
    const int w = threadIdx.x;

    __shared__ float sF0[8 * 649];     // c-stride 649 (bank spread)
    __shared__ float sF1[8 * 65];
    __shared__ float sInv0[9 * 72];
    __shared__ float sInv1[64];

    float acc[81];
#pragma unroll
    for (int o = 0; o < 81; o++) acc[o] = 0.f;

    const float* f0b = g_feat + (size_t)b * H * W * 128;
    const float* f1b = g_feat + (size_t)(b + 32) * H * W * 128;

    sInv1[w] = g_inv[((size_t)(b + 32) * H + h) * W + w];
    for (int i = w; i < 9 * 72; i += 64) {
        int r  = i / 72;
        int cc = i % 72;
        int gh = h + r - 4;
        int gw = cc - 4;
        float v = 0.f;
        if (gh >= 0 && gh < H && gw >= 0 && gw < W)
            v = g_inv[((size_t)b * H + gh) * W + gw];
        sInv0[i] = v;
    }
    __syncthreads();

    for (int c0 = 0; c0 < 128; c0 += 8) {
        for (int i = w; i < 8 * 64; i += 64) {
            int c = i & 7, ww = i >> 3;
            sF1[c * 65 + ww] = f1b[((size_t)h * W + ww) * 128 + c0 + c] * sInv1[ww];
        }
        for (int i = w; i < 8 * 648; i += 64) {
            int c   = i & 7;
            int pix = i >> 3;              // r*72 + cc
            int r  = pix / 72;
            int cc = pix % 72;
            int gh = h + r - 4;
            int gw = cc - 4;
            float v = 0.f;
            if (gh >= 0 && gh < H && gw >= 0 && gw < W)
                v = f0b[((size_t)gh * W + gw) * 128 + c0 + c] * sInv0[pix];
            sF0[c * 649 + pix] = v;
        }
        __syncthreads();
#pragma unroll
        for (int c = 0; c < 8; c++) {
            float iv = sF1[c * 65 + w];
#pragma unroll
            for (int r = 0; r < 9; r++)
#pragma unroll
                for (int d = 0; d < 9; d++)
                    acc[r * 9 + d] = fmaf(sF0[c * 649 + r * 72 + w + d], iv, acc[r * 9 + d]);
        }
        __syncthreads();
    }
    float* dst = g_concat + ((size_t)(b * H + h) * W + w) * 216;
#pragma unroll
    for (int o = 0; o < 81; o++) dst[o] = round_tf32(acc[o]);
}

// ------------------------- f1 copy + pad into concat (coalesced) -----------
__global__ void copy_f1_kernel() {
    int i = blockIdx.x * 256 + threadIdx.x;     // over 32*48*64*135
    const int TOT = 32 * 48 * 64 * 135;
    if (i >= TOT) return;
    int c   = i % 135;
    int pix = i / 135;
    float v = 0.f;
    if (c < 128) v = g_feat[((size_t)pix + (size_t)32 * 48 * 64) * 128 + c];
    g_concat[(size_t)pix * 216 + 81 + c] = v;
}

// ------------------------- global average pool (NHWC) ----------------------
__global__ void __launch_bounds__(256)
avgpool_kernel(float* __restrict__ out) {
    int b = blockIdx.x;
    int c = threadIdx.x;
    const float* p = g_y2 + (size_t)b * 768 * 256 + c;
    float s = 0.f;
#pragma unroll 8
    for (int i = 0; i < 768; i++) s += p[(size_t)i * 256];
    out[b * 256 + c] = s * (1.0f / 768.0f);
}

// ---------------------------------------------------------------------------
extern "C" void kernel_launch(void* const* d_in, const int* in_sizes, int n_in,
                              void* d_out, int out_size) {
    (void)in_sizes; (void)n_in; (void)out_size;

    const float* img0 = (const float*)d_in[0];
    const float* img1 = (const float*)d_in[1];
    const float* w1 = (const float*)d_in[2];  const float* b1 = (const float*)d_in[3];
    const float* g1 = (const float*)d_in[4];  const float* be1 = (const float*)d_in[5];
    const float* m1 = (const float*)d_in[6];  const float* v1 = (const float*)d_in[7];
    const float* w2 = (const float*)d_in[8];  const float* b2 = (const float*)d_in[9];
    const float* g2 = (const float*)d_in[10]; const float* be2 = (const float*)d_in[11];
    const float* m2 = (const float*)d_in[12]; const float* v2 = (const float*)d_in[13];
    const float* w3 = (const float*)d_in[14]; const float* b3 = (const float*)d_in[15];
    const float* g3 = (const float*)d_in[16]; const float* be3 = (const float*)d_in[17];
    const float* m3 = (const float*)d_in[18]; const float* v3 = (const float*)d_in[19];
    const float* wf1 = (const float*)d_in[20]; const float* bf1 = (const float*)d_in[21];
    const float* gf1 = (const float*)d_in[22]; const float* bef1 = (const float*)d_in[23];
    const float* mf1 = (const float*)d_in[24]; const float* vf1 = (const float*)d_in[25];
    const float* wf2 = (const float*)d_in[26]; const float* bf2 = (const float*)d_in[27];
    const float* gf2 = (const float*)d_in[28]; const float* bef2 = (const float*)d_in[29];
    const float* mf2 = (const float*)d_in[30]; const float* vf2 = (const float*)d_in[31];

    // --- fold BN params ---
    bn_prep_kernel<<<1, 256>>>(g1, be1, m1, v1, b1, 0, 32);
    bn_prep_kernel<<<1, 256>>>(g2, be2, m2, v2, b2, 32, 64);
    bn_prep_kernel<<<1, 256>>>(g3, be3, m3, v3, b3, 96, 128);
    bn_prep_kernel<<<1, 256>>>(gf1, bef1, mf1, vf1, bf1, 224, 256);
    bn_prep_kernel<<<1, 256>>>(gf2, bef2, mf2, vf2, bf2, 480, 256);

    // --- weight transforms (tf32 + scale fold) ---
    wt_prep_kernel<<<(12544 + 255) / 256, 256>>>(w1, 3, 32, 49, 4, 1, 0, 0, 12544);
    wt_prep_kernel<<<(51200 + 255) / 256, 256>>>(w2, 32, 64, 25, 8, 4, 12544, 32, 51200);
    wt_prep_kernel<<<(73728 + 255) / 256, 256>>>(w3, 64, 64, 9, 8, 8, 63744, 96, 73728);
    wt_prep_kernel<<<(497664 + 255) / 256, 256>>>(wf1, 209, 64, 9, 8, 27, 137472, 224, 497664);
    wt_prep_kernel<<<(589824 + 255) / 256, 256>>>(wf2, 256, 64, 9, 8, 32, 635136, 480, 589824);

    // --- conv1: 7x7 s2, NCHW imgs (merged 64) -> act1 (tf32-rounded) ---
    {
        auto k = conv_mma<8, 3, 32, 32, 7, 2, 3, 16, 16, 384, 512, 192, 256, BUF_EXT, BUF_ACT1, true>;
        int sm = (((37 * 37 * 10 + 3) & ~3) + 49 * 32 * 8) * 4;           // 104,944
        cudaFuncSetAttribute(k, cudaFuncAttributeMaxDynamicSharedMemorySize, sm);
        k<<<dim3(16, 12, 64), 512, sm>>>(img0, img1, 0, 0);
    }
    // --- conv2: 5x5 s2 -> act2 ---
    {
        auto k = conv_mma<32, 32, 64, 64, 5, 2, 2, 16, 16, 192, 256, 96, 128, BUF_ACT1, BUF_ACT2, true>;
        int sm = 2 * (((35 * 35 * 10 + 3) & ~3) + 25 * 64 * 8) * 4;       // 200,416
        cudaFuncSetAttribute(k, cudaFuncAttributeMaxDynamicSharedMemorySize, sm);
        k<<<dim3(8, 6, 64), 512, sm>>>(nullptr, nullptr, 12544, 32);
    }
    // --- conv3: 3x3 s2 -> feat ---
    {
        auto k = conv_mma<64, 64, 128, 64, 3, 2, 1, 8, 32, 96, 128, 48, 64, BUF_ACT2, BUF_FEAT, true>;
        int sm = 2 * (((17 * 65 * 10 + 3) & ~3) + 9 * 64 * 8) * 4;        // 125,280
        cudaFuncSetAttribute(k, cudaFuncAttributeMaxDynamicSharedMemorySize, sm);
        k<<<dim3(2, 6, 128), 512, sm>>>(nullptr, nullptr, 63744, 96);
    }

    // --- inverse L2 norms (all 64 feature maps) ---
    l2inv_kernel<<<(64 * 48 * 64) / 8, 256>>>();

    // --- correlation + f1 copy into concat ---
    corr_kernel<<<dim3(48, 32), 64>>>();
    copy_f1_kernel<<<(32 * 48 * 64 * 135 + 255) / 256, 256>>>();

    // --- convf1: 3x3 s2 -> y1 ---
    {
        auto k = conv_mma<216, 209, 256, 64, 3, 2, 1, 8, 32, 48, 64, 24, 32, BUF_CONCAT, BUF_Y1, true>;
        int sm = 2 * (((17 * 65 * 10 + 3) & ~3) + 9 * 64 * 8) * 4;        // 125,280
        cudaFuncSetAttribute(k, cudaFuncAttributeMaxDynamicSharedMemorySize, sm);
        k<<<dim3(1, 3, 128), 512, sm>>>(nullptr, nullptr, 137472, 224);
    }
    // --- convf2: 3x3 s1 -> y2 (final, unrounded) ---
    {
        auto k = conv_mma<256, 256, 256, 64, 3, 1, 1, 8, 32, 24, 32, 24, 32, BUF_Y1, BUF_Y2, false>;
        int sm = 2 * ((10 * 34 * 10) + 9 * 64 * 8) * 4;                   // 64,064
        cudaFuncSetAttribute(k, cudaFuncAttributeMaxDynamicSharedMemorySize, sm);
        k<<<dim3(1, 3, 128), 512, sm>>>(nullptr, nullptr, 635136, 480);
    }

    // --- global average pool -> (32,256) ---
    avgpool_kernel<<<32, 256>>>((float*)d_out);
}

// round 9
// speedup vs baseline: 4.0399x; 1.0510x over previous
#include <cuda_runtime.h>
#include <math.h>

typedef unsigned int uint32;

#define BATCH 32

// ---------------------------------------------------------------------------
// FlowEncoder — tf32 tensor-core implicit GEMM, cp.async double-buffered.
// 32x32 warp tiles; conv1 packs (kx,c) into the MMA K-dim (6/8 slots used).
// ---------------------------------------------------------------------------

// ------------------------- device scratch (no allocs) ----------------------
__device__ __align__(16) float g_act1[(size_t)64 * 192 * 256 * 32];
__device__ __align__(16) float g_act2[(size_t)64 * 96 * 128 * 64];
__device__ __align__(16) float g_feat[(size_t)64 * 48 * 64 * 128];
__device__ __align__(16) float g_concat[(size_t)32 * 48 * 64 * 216];
__device__ __align__(16) float g_y1[(size_t)32 * 24 * 32 * 256];
__device__ __align__(16) float g_y2[(size_t)32 * 24 * 32 * 256];
__device__ float g_inv[(size_t)64 * 48 * 64];
__device__ __align__(16) uint32 g_wt[1224960];   // transformed tf32 weights
__device__ float g_scale[736];
__device__ float g_bias[736];

enum { BUF_EXT = 0, BUF_ACT1, BUF_ACT2, BUF_FEAT, BUF_CONCAT, BUF_Y1, BUF_Y2 };

__device__ __forceinline__ float* get_buf(int id) {
    switch (id) {
        case BUF_ACT1:   return g_act1;
        case BUF_ACT2:   return g_act2;
        case BUF_FEAT:   return g_feat;
        case BUF_CONCAT: return g_concat;
        case BUF_Y1:     return g_y1;
        case BUF_Y2:     return g_y2;
        default:         return nullptr;
    }
}

// ------------------------- helpers -----------------------------------------
__device__ __forceinline__ uint32 to_tf32(float f) {
    uint32 u; asm("cvt.rna.tf32.f32 %0, %1;" : "=r"(u) : "f"(f)); return u;
}
__device__ __forceinline__ float round_tf32(float f) {
    return __uint_as_float(to_tf32(f));
}
__device__ __forceinline__ void mma_tf32(float* d, uint32 a0, uint32 a1, uint32 a2, uint32 a3,
                                         uint32 b0, uint32 b1) {
    asm volatile(
        "mma.sync.aligned.m16n8k8.row.col.f32.tf32.tf32.f32 "
        "{%0,%1,%2,%3},{%4,%5,%6,%7},{%8,%9},{%0,%1,%2,%3};"
        : "+f"(d[0]), "+f"(d[1]), "+f"(d[2]), "+f"(d[3])
        : "r"(a0), "r"(a1), "r"(a2), "r"(a3), "r"(b0), "r"(b1));
}
__device__ __forceinline__ void cp_async8(uint32 dst, const void* src) {
    asm volatile("cp.async.ca.shared.global [%0], [%1], 8;" :: "r"(dst), "l"(src));
}
__device__ __forceinline__ void cp_async16(uint32 dst, const void* src) {
    asm volatile("cp.async.ca.shared.global [%0], [%1], 16;" :: "r"(dst), "l"(src));
}
__device__ __forceinline__ void cp_commit() { asm volatile("cp.async.commit_group;"); }
__device__ __forceinline__ void cp_wait0()  { asm volatile("cp.async.wait_group 0;"); }
__device__ __forceinline__ void cp_wait1()  { asm volatile("cp.async.wait_group 1;"); }

// ------------------------- BN folding (single launch) ----------------------
__global__ void bn_prep_all(
    const float* g1, const float* be1, const float* m1, const float* v1, const float* b1,
    const float* g2, const float* be2, const float* m2, const float* v2, const float* b2,
    const float* g3, const float* be3, const float* m3, const float* v3, const float* b3,
    const float* gf1, const float* bef1, const float* mf1, const float* vf1, const float* bf1,
    const float* gf2, const float* bef2, const float* mf2, const float* vf2, const float* bf2) {
    int i = blockIdx.x * blockDim.x + threadIdx.x;
    if (i >= 736) return;
    const float *g, *be, *m, *v, *cb; int li;
    if (i < 32)       { g=g1;  be=be1;  m=m1;  v=v1;  cb=b1;  li=i; }
    else if (i < 96)  { g=g2;  be=be2;  m=m2;  v=v2;  cb=b2;  li=i-32; }
    else if (i < 224) { g=g3;  be=be3;  m=m3;  v=v3;  cb=b3;  li=i-96; }
    else if (i < 480) { g=gf1; be=bef1; m=mf1; v=vf1; cb=bf1; li=i-224; }
    else              { g=gf2; be=bef2; m=mf2; v=vf2; cb=bf2; li=i-480; }
    float s = g[li] / sqrtf(v[li] + 1e-5f);
    g_scale[i] = s;
    g_bias[i]  = (cb[li] - m[li]) * s + be[li];
}

// ------------------------- weight transforms -------------------------------
// generic layout (NT=64, NTILES=8): [nb][chunk][tap][j][k][n8]
__device__ __forceinline__ void wt_generic(const float* __restrict__ W, int li,
                                           int ICR, int KK, int NCHUNK,
                                           int wt_off, int bn_off) {
    int n8    = li & 7;
    int k     = (li >> 3) & 7;
    int j     = (li >> 6) & 7;
    int tap   = (li >> 9) % KK;
    int chunk = (li / (512 * KK)) % NCHUNK;
    int nb    = li / (512 * KK * NCHUNK);
    int oc = nb * 64 + j * 8 + n8;
    int ic = chunk * 8 + k;
    float val = 0.f;
    if (ic < ICR)
        val = W[((size_t)oc * ICR + ic) * KK + tap] * g_scale[bn_off + oc];
    g_wt[wt_off + li] = to_tf32(val);
}

// conv1 special: K-dim packs (kx_local, c): k = c + 3*kxl, chunk p covers kx {2p,2p+1}
// layout [ky7][p4][j4][k8][n8], 7168 words @0
__global__ void wt_prep_123(const float* __restrict__ w1,
                            const float* __restrict__ w2,
                            const float* __restrict__ w3) {
    int i = blockIdx.x * blockDim.x + threadIdx.x;
    if (i < 7168) {
        int n8 = i & 7;
        int k  = (i >> 3) & 7;
        int j  = (i >> 6) & 3;
        int p  = (i >> 8) & 3;
        int ky = i >> 10;
        int oc = j * 8 + n8;
        int c  = k % 3;
        int kx = 2 * p + k / 3;
        float val = 0.f;
        if (k < 6 && kx <= 6)
            val = w1[oc * 147 + c * 49 + ky * 7 + kx] * g_scale[oc];
        g_wt[i] = to_tf32(val);
    } else if (i < 58368) {
        wt_generic(w2, i - 7168, 32, 25, 4, 7168, 32);
    } else if (i < 132096) {
        wt_generic(w3, i - 58368, 64, 9, 8, 58368, 96);
    }
}
__global__ void wt_prep_one(const float* __restrict__ W, int ICR, int KK, int NCHUNK,
                            int wt_off, int bn_off, int total) {
    int i = blockIdx.x * blockDim.x + threadIdx.x;
    if (i < total) wt_generic(W, i, ICR, KK, NCHUNK, wt_off, bn_off);
}

// ------------------------- conv1 (7x7 s2, K-packed) ------------------------
// 512 thr = 16 warps, each 32x32 warp tile; block M=512 (16x32 tile), N=32.
__global__ void __launch_bounds__(512)
conv1_mma(const float* __restrict__ img0, const float* __restrict__ img1) {
    constexpr int INTH = 37, INTW = 69, NPIX = INTH * INTW;       // 2553
    constexpr int SIN_PAD = (NPIX * 10 + 3) & ~3;                 // 25532
    constexpr int SW_SZ = 7168;

    extern __shared__ __align__(16) uint32 smem[];
    uint32* sIn = smem;
    uint32* sW  = smem + SIN_PAD;
    const uint32 smem_b = (uint32)__cvta_generic_to_shared(smem);

    const int tid  = threadIdx.x;
    const int lane = tid & 31;
    const int wid  = tid >> 5;

    const int b   = blockIdx.z;
    const int oh0 = blockIdx.y * 16;
    const int ow0 = blockIdx.x * 32;
    const int ir0 = oh0 * 2 - 3;
    const int ic0 = ow0 * 2 - 3;

    const float* in = (b < 32 ? img0 : img1) + (size_t)(b & 31) * 3 * 384 * 512;

    // stage weights async while filling input
    for (int i = tid; i < SW_SZ / 4; i += 512)
        cp_async16(smem_b + (SIN_PAD + i * 4) * 4, g_wt + i * 4);
    cp_commit();

    for (int i = tid; i < NPIX * 10; i += 512) sIn[i] = 0;
    __syncthreads();
    for (int i = tid; i < NPIX * 3; i += 512) {
        int c = i / NPIX, pix = i % NPIX;
        int r = pix / INTW, cc = pix % INTW;
        int gr = ir0 + r, gc = ic0 + cc;
        if (gr >= 0 && gr < 384 && gc >= 0 && gc < 512)
            sIn[pix * 10 + c] = to_tf32(in[(size_t)c * 384 * 512 + (size_t)gr * 512 + gc]);
    }
    cp_wait0();
    __syncthreads();

    // fragment bases
    const int mgrp = wid * 32;
    const int jlo = lane & 3;
    const int jc  = (jlo + 4 > 5) ? 5 : (jlo + 4);
    int abase[4];
#pragma unroll
    for (int r = 0; r < 4; r++) {
        int pm = mgrp + (lane >> 2) + 8 * r;
        abase[r] = (((pm >> 5) * 2) * INTW + (pm & 31) * 2) * 10;
    }
    int clo[4], chi[4];
#pragma unroll
    for (int p = 0; p < 4; p++) {
        int kxl = 2 * p + jlo / 3; if (kxl > 6) kxl = 6;
        clo[p] = kxl * 10 + jlo % 3;
        int kxh = 2 * p + jc / 3;  if (kxh > 6) kxh = 6;
        chi[p] = kxh * 10 + jc % 3;
    }
    const int bbase = (lane & 3) * 8 + (lane >> 2);

    float acc[2][4][4];
#pragma unroll
    for (int s = 0; s < 2; s++)
#pragma unroll
        for (int j = 0; j < 4; j++)
#pragma unroll
            for (int q = 0; q < 4; q++) acc[s][j][q] = 0.f;

#pragma unroll
    for (int ky = 0; ky < 7; ky++) {
        const int kyo = ky * INTW * 10;
#pragma unroll
        for (int p = 0; p < 4; p++) {
            uint32 Al[4], Ah[4];
#pragma unroll
            for (int r = 0; r < 4; r++) {
                Al[r] = sIn[abase[r] + kyo + clo[p]];
                Ah[r] = sIn[abase[r] + kyo + chi[p]];
            }
            const int tbase = ((ky * 4 + p) * 4) * 64;
#pragma unroll
            for (int j = 0; j < 4; j++) {
                uint32 B0 = sW[tbase + j * 64 + bbase];
                uint32 B1 = sW[tbase + j * 64 + bbase + 32];
                mma_tf32(acc[0][j], Al[0], Al[1], Ah[0], Ah[1], B0, B1);
                mma_tf32(acc[1][j], Al[2], Al[3], Ah[2], Ah[3], B0, B1);
            }
        }
    }

    // epilogue
    float* outp = g_act1 + (size_t)b * 192 * 256 * 32;
#pragma unroll
    for (int s = 0; s < 2; s++) {
#pragma unroll
        for (int hr = 0; hr < 2; hr++) {
            int pm = mgrp + (lane >> 2) + 16 * s + 8 * hr;
            int goh = oh0 + (pm >> 5), gow = ow0 + (pm & 31);
#pragma unroll
            for (int j = 0; j < 4; j++) {
                int oc = j * 8 + (lane & 3) * 2;
                float v0 = fmaxf(acc[s][j][2 * hr]     + g_bias[oc],     0.f);
                float v1 = fmaxf(acc[s][j][2 * hr + 1] + g_bias[oc + 1], 0.f);
                *(float2*)&outp[((size_t)goh * 256 + gow) * 32 + oc] =
                    make_float2(round_tf32(v0), round_tf32(v1));
            }
        }
    }
}

// ------------------------- generic conv (NT=64, 32x32 warp tiles) ----------
// 512 thr = 16 warps = 8 M-groups x 2 N-groups. Block M=256, N=64.
template <int ICP, int OC, int K, int S, int P,
          int TOH, int TOW, int IH, int IW, int OH, int OW,
          int INBUF, int OUTBUF, bool ROUND_OUT>
__global__ void __launch_bounds__(512)
conv_mma(int wt_off, int bn_off) {
    constexpr int INTH    = (TOH - 1) * S + K;
    constexpr int INTW    = (TOW - 1) * S + K;
    constexpr int NPIX    = INTH * INTW;
    constexpr int NCHUNK  = ICP / 8;
    constexpr int NOCB    = OC / 64;
    constexpr int SIN_PAD = (NPIX * 10 + 3) & ~3;
    constexpr int SW_SZ   = K * K * 64 * 8;

    extern __shared__ __align__(16) uint32 smem[];
    const uint32 smem_b = (uint32)__cvta_generic_to_shared(smem);

    const int tid  = threadIdx.x;
    const int lane = tid & 31;
    const int wid  = tid >> 5;

    const int b   = blockIdx.z / NOCB;
    const int nb  = blockIdx.z % NOCB;
    const int oc0 = nb * 64;
    const int oh0 = blockIdx.y * TOH;
    const int ow0 = blockIdx.x * TOW;
    const int ir0 = oh0 * S - P;
    const int ic0 = ow0 * S - P;

    const float* in_nhwc = get_buf(INBUF) + (size_t)b * IH * IW * ICP;
    const uint32* wt = g_wt + wt_off + (size_t)nb * NCHUNK * SW_SZ;

    float acc[2][4][4];
#pragma unroll
    for (int s = 0; s < 2; s++)
#pragma unroll
        for (int j = 0; j < 4; j++)
#pragma unroll
            for (int q = 0; q < 4; q++) acc[s][j][q] = 0.f;

    // fragment bases: warp = (wid>>1) M-group x (wid&1) N-group
    const int mgrp = (wid >> 1) * 32;
    const int ntg  = (wid & 1) * 4;
    int abase[4];
#pragma unroll
    for (int r = 0; r < 4; r++) {
        int pm = mgrp + (lane >> 2) + 8 * r;
        abase[r] = (((pm / TOW) * S) * INTW + (pm % TOW) * S) * 10 + (lane & 3);
    }
    const int bbase = (lane & 3) * 8 + (lane >> 2);

    auto do_mma = [&](const uint32* sInb, const uint32* sWb) {
#pragma unroll
        for (int ky = 0; ky < K; ky++) {
#pragma unroll
            for (int kx = 0; kx < K; kx++) {
                const int aoff = (ky * INTW + kx) * 10;
                uint32 Al[4], Ah[4];
#pragma unroll
                for (int r = 0; r < 4; r++) {
                    Al[r] = sInb[abase[r] + aoff];
                    Ah[r] = sInb[abase[r] + aoff + 4];
                }
                const int tapoff = (ky * K + kx) * 512;
#pragma unroll
                for (int j = 0; j < 4; j++) {
                    uint32 B0 = sWb[tapoff + (ntg + j) * 64 + bbase];
                    uint32 B1 = sWb[tapoff + (ntg + j) * 64 + bbase + 32];
                    mma_tf32(acc[0][j], Al[0], Al[1], Ah[0], Ah[1], B0, B1);
                    mma_tf32(acc[1][j], Al[2], Al[3], Ah[2], Ah[3], B0, B1);
                }
            }
        }
    };

    const int inO0 = 0, inO1 = SIN_PAD;
    const int wO0  = 2 * SIN_PAD, wO1 = 2 * SIN_PAD + SW_SZ;

    // pre-zero boundary pixels (disjoint from cp.async targets)
    for (int pix = tid; pix < NPIX; pix += 512) {
        int r = pix / INTW, cc = pix % INTW;
        int gr = ir0 + r, gc = ic0 + cc;
        if (!(gr >= 0 && gr < IH && gc >= 0 && gc < IW)) {
#pragma unroll
            for (int c = 0; c < 8; c++) {
                smem[inO0 + pix * 10 + c] = 0;
                smem[inO1 + pix * 10 + c] = 0;
            }
        }
    }

    auto stage_in = [&](int chunk, int off) {
        const float* base = in_nhwc + chunk * 8;
        for (int pix = tid; pix < NPIX; pix += 512) {
            int r = pix / INTW, cc = pix % INTW;
            int gr = ir0 + r, gc = ic0 + cc;
            if (gr >= 0 && gr < IH && gc >= 0 && gc < IW) {
                const float* s = base + ((size_t)gr * IW + gc) * ICP;
                uint32 d = smem_b + (off + pix * 10) * 4;
                cp_async8(d,      s);
                cp_async8(d + 8,  s + 2);
                cp_async8(d + 16, s + 4);
                cp_async8(d + 24, s + 6);
            }
        }
    };
    auto stage_w = [&](int chunk, int off) {
        const uint32* s = wt + (size_t)chunk * SW_SZ;
        uint32 d = smem_b + off * 4;
        for (int i = tid; i < SW_SZ / 4; i += 512)
            cp_async16(d + i * 16, s + i * 4);
    };

    stage_in(0, inO0); stage_w(0, wO0); cp_commit();
    for (int ch = 0; ch < NCHUNK; ch++) {
        if (ch + 1 < NCHUNK) {
            int nxt = (ch + 1) & 1;
            stage_in(ch + 1, nxt ? inO1 : inO0);
            stage_w(ch + 1, nxt ? wO1 : wO0);
            cp_commit();
            cp_wait1();
        } else {
            cp_wait0();
        }
        __syncthreads();
        int cur = ch & 1;
        do_mma(smem + (cur ? inO1 : inO0), smem + (cur ? wO1 : wO0));
        __syncthreads();
    }

    // epilogue
    float* outp = get_buf(OUTBUF) + (size_t)b * OH * OW * OC;
#pragma unroll
    for (int s = 0; s < 2; s++) {
#pragma unroll
        for (int hr = 0; hr < 2; hr++) {
            int pm = mgrp + (lane >> 2) + 16 * s + 8 * hr;
            int goh = oh0 + pm / TOW, gow = ow0 + pm % TOW;
#pragma unroll
            for (int j = 0; j < 4; j++) {
                int oc = oc0 + (ntg + j) * 8 + (lane & 3) * 2;
                float v0 = fmaxf(acc[s][j][2 * hr]     + g_bias[bn_off + oc],     0.f);
                float v1 = fmaxf(acc[s][j][2 * hr + 1] + g_bias[bn_off + oc + 1], 0.f);
                if (ROUND_OUT) { v0 = round_tf32(v0); v1 = round_tf32(v1); }
                *(float2*)&outp[((size_t)goh * OW + gow) * OC + oc] = make_float2(v0, v1);
            }
        }
    }
}

// ------------------------- per-pixel inverse L2 norm -----------------------
__global__ void __launch_bounds__(256) l2inv_kernel() {
    int pix  = blockIdx.x * 8 + (threadIdx.x >> 5);
    int lane = threadIdx.x & 31;
    float4 v = *(const float4*)&g_feat[(size_t)pix * 128 + lane * 4];
    float ss = v.x * v.x + v.y * v.y + v.z * v.z + v.w * v.w;
#pragma unroll
    for (int o = 16; o > 0; o >>= 1) ss += __shfl_xor_sync(0xFFFFFFFFu, ss, o);
    if (lane == 0) g_inv[pix] = 1.0f / fmaxf(sqrtf(ss), 1e-12f);
}

// ------------------------- correlation volume (NHWC, coalesced) ------------
__global__ void __launch_bounds__(64)
corr_kernel() {
    const int H = 48, W = 64;
    const int h = blockIdx.x;
    const int b = blockIdx.y;
    const int w = threadIdx.x;

    __shared__ float sF0[8 * 649];
    __shared__ float sF1[8 * 65];
    __shared__ float sInv0[9 * 72];
    __shared__ float sInv1[64];

    float acc[81];
#pragma unroll
    for (int o = 0; o < 81; o++) acc[o] = 0.f;

    const float* f0b = g_feat + (size_t)b * H * W * 128;
    const float* f1b = g_feat + (size_t)(b + 32) * H * W * 128;

    sInv1[w] = g_inv[((size_t)(b + 32) * H + h) * W + w];
    for (int i = w; i < 9 * 72; i += 64) {
        int r  = i / 72;
        int cc = i % 72;
        int gh = h + r - 4;
        int gw = cc - 4;
        float v = 0.f;
        if (gh >= 0 && gh < H && gw >= 0 && gw < W)
            v = g_inv[((size_t)b * H + gh) * W + gw];
        sInv0[i] = v;
    }
    __syncthreads();

    for (int c0 = 0; c0 < 128; c0 += 8) {
        for (int i = w; i < 8 * 64; i += 64) {
            int c = i & 7, ww = i >> 3;
            sF1[c * 65 + ww] = f1b[((size_t)h * W + ww) * 128 + c0 + c] * sInv1[ww];
        }
        for (int i = w; i < 8 * 648; i += 64) {
            int c   = i & 7;
            int pix = i >> 3;
            int r  = pix / 72;
            int cc = pix % 72;
            int gh = h + r - 4;
            int gw = cc - 4;
            float v = 0.f;
            if (gh >= 0 && gh < H && gw >= 0 && gw < W)
                v = f0b[((size_t)gh * W + gw) * 128 + c0 + c] * sInv0[pix];
            sF0[c * 649 + pix] = v;
        }
        __syncthreads();
#pragma unroll
        for (int c = 0; c < 8; c++) {
            float iv = sF1[c * 65 + w];
#pragma unroll
            for (int r = 0; r < 9; r++)
#pragma unroll
                for (int d = 0; d < 9; d++)
                    acc[r * 9 + d] = fmaf(sF0[c * 649 + r * 72 + w + d], iv, acc[r * 9 + d]);
        }
        __syncthreads();
    }
    float* dst = g_concat + ((size_t)(b * H + h) * W + w) * 216;
#pragma unroll
    for (int o = 0; o < 81; o++) dst[o] = round_tf32(acc[o]);
}

// ------------------------- f1 copy + pad into concat -----------------------
__global__ void copy_f1_kernel() {
    int i = blockIdx.x * 256 + threadIdx.x;
    const int TOT = 32 * 48 * 64 * 135;
    if (i >= TOT) return;
    int c   = i % 135;
    int pix = i / 135;
    float v = 0.f;
    if (c < 128) v = g_feat[((size_t)pix + (size_t)32 * 48 * 64) * 128 + c];
    g_concat[(size_t)pix * 216 + 81 + c] = v;
}

// ------------------------- global average pool -----------------------------
__global__ void __launch_bounds__(256)
avgpool_kernel(float* __restrict__ out) {
    int b = blockIdx.x;
    int c = threadIdx.x;
    const float* p = g_y2 + (size_t)b * 768 * 256 + c;
    float s = 0.f;
#pragma unroll 8
    for (int i = 0; i < 768; i++) s += p[(size_t)i * 256];
    out[b * 256 + c] = s * (1.0f / 768.0f);
}

// ---------------------------------------------------------------------------
extern "C" void kernel_launch(void* const* d_in, const int* in_sizes, int n_in,
                              void* d_out, int out_size) {
    (void)in_sizes; (void)n_in; (void)out_size;

    const float* img0 = (const float*)d_in[0];
    const float* img1 = (const float*)d_in[1];
    const float* w1 = (const float*)d_in[2];  const float* b1 = (const float*)d_in[3];
    const float* g1 = (const float*)d_in[4];  const float* be1 = (const float*)d_in[5];
    const float* m1 = (const float*)d_in[6];  const float* v1 = (const float*)d_in[7];
    const float* w2 = (const float*)d_in[8];  const float* b2 = (const float*)d_in[9];
    const float* g2 = (const float*)d_in[10]; const float* be2 = (const float*)d_in[11];
    const float* m2 = (const float*)d_in[12]; const float* v2 = (const float*)d_in[13];
    const float* w3 = (const float*)d_in[14]; const float* b3 = (const float*)d_in[15];
    const float* g3 = (const float*)d_in[16]; const float* be3 = (const float*)d_in[17];
    const float* m3 = (const float*)d_in[18]; const float* v3 = (const float*)d_in[19];
    const float* wf1 = (const float*)d_in[20]; const float* bf1 = (const float*)d_in[21];
    const float* gf1 = (const float*)d_in[22]; const float* bef1 = (const float*)d_in[23];
    const float* mf1 = (const float*)d_in[24]; const float* vf1 = (const float*)d_in[25];
    const float* wf2 = (const float*)d_in[26]; const float* bf2 = (const float*)d_in[27];
    const float* gf2 = (const float*)d_in[28]; const float* bef2 = (const float*)d_in[29];
    const float* mf2 = (const float*)d_in[30]; const float* vf2 = (const float*)d_in[31];

    // (1) BN fold — one launch
    bn_prep_all<<<3, 256>>>(g1, be1, m1, v1, b1, g2, be2, m2, v2, b2,
                            g3, be3, m3, v3, b3, gf1, bef1, mf1, vf1, bf1,
                            gf2, bef2, mf2, vf2, bf2);
    // (2) weights conv1+2+3 — one launch  [conv1 @0 (7168), conv2 @7168, conv3 @58368]
    wt_prep_123<<<(132096 + 255) / 256, 256>>>(w1, w2, w3);
    // (3) wf1 @132096, (4) wf2 @629760
    wt_prep_one<<<(497664 + 255) / 256, 256>>>(wf1, 209, 9, 27, 132096, 224, 497664);
    wt_prep_one<<<(589824 + 255) / 256, 256>>>(wf2, 256, 9, 32, 629760, 480, 589824);

    // (5) conv1: M=512 blocks, K-packed
    {
        int sm = (((37 * 69 * 10 + 3) & ~3) + 7168) * 4;                  // 130,800
        cudaFuncSetAttribute(conv1_mma, cudaFuncAttributeMaxDynamicSharedMemorySize, sm);
        conv1_mma<<<dim3(8, 12, 64), 512, sm>>>(img0, img1);
    }
    // (6) conv2 — profiled by ncu (-s 5 -c 1)
    {
        auto k = conv_mma<32, 64, 5, 2, 2, 16, 16, 192, 256, 96, 128, BUF_ACT1, BUF_ACT2, true>;
        int sm = 2 * (((35 * 35 * 10 + 3) & ~3) + 25 * 64 * 8) * 4;       // 200,416
        cudaFuncSetAttribute(k, cudaFuncAttributeMaxDynamicSharedMemorySize, sm);
        k<<<dim3(8, 6, 64), 512, sm>>>(7168, 32);
    }
    // (7) conv3
    {
        auto k = conv_mma<64, 128, 3, 2, 1, 8, 32, 96, 128, 48, 64, BUF_ACT2, BUF_FEAT, true>;
        int sm = 2 * (((17 * 65 * 10 + 3) & ~3) + 9 * 64 * 8) * 4;        // 125,280
        cudaFuncSetAttribute(k, cudaFuncAttributeMaxDynamicSharedMemorySize, sm);
        k<<<dim3(2, 6, 128), 512, sm>>>(58368, 96);
    }

    // (8) inverse L2 norms
    l2inv_kernel<<<(64 * 48 * 64) / 8, 256>>>();
    // (9) correlation, (10) f1 copy
    corr_kernel<<<dim3(48, 32), 64>>>();
    copy_f1_kernel<<<(32 * 48 * 64 * 135 + 255) / 256, 256>>>();

    // (11) convf1
    {
        auto k = conv_mma<216, 256, 3, 2, 1, 8, 32, 48, 64, 24, 32, BUF_CONCAT, BUF_Y1, true>;
        int sm = 2 * (((17 * 65 * 10 + 3) & ~3) + 9 * 64 * 8) * 4;        // 125,280
        cudaFuncSetAttribute(k, cudaFuncAttributeMaxDynamicSharedMemorySize, sm);
        k<<<dim3(1, 3, 128), 512, sm>>>(132096, 224);
    }
    // (12) convf2
    {
        auto k = conv_mma<256, 256, 3, 1, 1, 8, 32, 24, 32, 24, 32, BUF_Y1, BUF_Y2, false>;
        int sm = 2 * ((10 * 34 * 10) + 9 * 64 * 8) * 4;                   // 64,064
        cudaFuncSetAttribute(k, cudaFuncAttributeMaxDynamicSharedMemorySize, sm);
        k<<<dim3(1, 3, 128), 512, sm>>>(629760, 480);
    }

    // (13) global average pool -> (32,256)
    avgpool_kernel<<<32, 256>>>((float*)d_out);
}

// round 10
// speedup vs baseline: 7.1305x; 1.7650x over previous
#include <cuda_runtime.h>
#include <cuda_fp16.h>
#include <math.h>

typedef unsigned int uint32;

// ---------------------------------------------------------------------------
// FlowEncoder — fp16 tensor-core implicit GEMM (mma.sync m16n8k16), f32 accum,
// cp.async double-buffered, NHWC __half activations.
// ---------------------------------------------------------------------------

// ------------------------- device scratch (no allocs) ----------------------
__device__ __align__(16) __half g_act1[(size_t)64 * 192 * 256 * 32];
__device__ __align__(16) __half g_act2[(size_t)64 * 96 * 128 * 64];
__device__ __align__(16) __half g_feat[(size_t)64 * 48 * 64 * 128];
__device__ __align__(16) __half g_concat[(size_t)32 * 48 * 64 * 224];
__device__ __align__(16) __half g_y1[(size_t)32 * 24 * 32 * 256];
__device__ __align__(16) float  g_y2[(size_t)32 * 24 * 32 * 256];
__device__ float g_inv[(size_t)64 * 48 * 64];
__device__ __align__(16) uint32 g_wt[619008];    // packed half2 weights
__device__ float g_scale[736];
__device__ float g_bias[736];

enum { BUF_ACT1 = 1, BUF_ACT2, BUF_FEAT, BUF_CONCAT, BUF_Y1, BUF_Y2 };

__device__ __forceinline__ __half* get_buf_h(int id) {
    switch (id) {
        case BUF_ACT1:   return g_act1;
        case BUF_ACT2:   return g_act2;
        case BUF_FEAT:   return g_feat;
        case BUF_CONCAT: return g_concat;
        case BUF_Y1:     return g_y1;
        default:         return nullptr;
    }
}

// ------------------------- helpers -----------------------------------------
__device__ __forceinline__ void mma_f16_k16(float* d, uint32 a0, uint32 a1, uint32 a2, uint32 a3,
                                            uint32 b0, uint32 b1) {
    asm volatile(
        "mma.sync.aligned.m16n8k16.row.col.f32.f16.f16.f32 "
        "{%0,%1,%2,%3},{%4,%5,%6,%7},{%8,%9},{%0,%1,%2,%3};"
        : "+f"(d[0]), "+f"(d[1]), "+f"(d[2]), "+f"(d[3])
        : "r"(a0), "r"(a1), "r"(a2), "r"(a3), "r"(b0), "r"(b1));
}
__device__ __forceinline__ void mma_f16_k8(float* d, uint32 a0, uint32 a1, uint32 b0) {
    asm volatile(
        "mma.sync.aligned.m16n8k8.row.col.f32.f16.f16.f32 "
        "{%0,%1,%2,%3},{%4,%5},{%6},{%0,%1,%2,%3};"
        : "+f"(d[0]), "+f"(d[1]), "+f"(d[2]), "+f"(d[3])
        : "r"(a0), "r"(a1), "r"(b0));
}
__device__ __forceinline__ void cp_async8(uint32 dst, const void* src) {
    asm volatile("cp.async.ca.shared.global [%0], [%1], 8;" :: "r"(dst), "l"(src));
}
__device__ __forceinline__ void cp_async16(uint32 dst, const void* src) {
    asm volatile("cp.async.ca.shared.global [%0], [%1], 16;" :: "r"(dst), "l"(src));
}
__device__ __forceinline__ void cp_commit() { asm volatile("cp.async.commit_group;"); }
__device__ __forceinline__ void cp_wait0()  { asm volatile("cp.async.wait_group 0;"); }
__device__ __forceinline__ void cp_wait1()  { asm volatile("cp.async.wait_group 1;"); }

__device__ __forceinline__ uint32 h2pack(float a, float b) {
    __half2 h = __floats2half2_rn(a, b);
    return *(uint32*)&h;
}

// ------------------------- BN folding (single launch) ----------------------
__global__ void bn_prep_all(
    const float* g1, const float* be1, const float* m1, const float* v1, const float* b1,
    const float* g2, const float* be2, const float* m2, const float* v2, const float* b2,
    const float* g3, const float* be3, const float* m3, const float* v3, const float* b3,
    const float* gf1, const float* bef1, const float* mf1, const float* vf1, const float* bf1,
    const float* gf2, const float* bef2, const float* mf2, const float* vf2, const float* bf2) {
    int i = blockIdx.x * blockDim.x + threadIdx.x;
    if (i >= 736) return;
    const float *g, *be, *m, *v, *cb; int li;
    if (i < 32)       { g=g1;  be=be1;  m=m1;  v=v1;  cb=b1;  li=i; }
    else if (i < 96)  { g=g2;  be=be2;  m=m2;  v=v2;  cb=b2;  li=i-32; }
    else if (i < 224) { g=g3;  be=be3;  m=m3;  v=v3;  cb=b3;  li=i-96; }
    else if (i < 480) { g=gf1; be=bef1; m=mf1; v=vf1; cb=bf1; li=i-224; }
    else              { g=gf2; be=bef2; m=mf2; v=vf2; cb=bf2; li=i-480; }
    float s = g[li] / sqrtf(v[li] + 1e-5f);
    g_scale[i] = s;
    g_bias[i]  = (cb[li] - m[li]) * s + be[li];
}

// ------------------------- weight transform (ALL layers, one launch) -------
// generic word layout: [nb][chunk(K16)][tap][j8][kp8][n8] = half2(ic0, ic0+1)
__device__ __forceinline__ void wt_generic(const float* __restrict__ W, int li,
                                           int ICR, int KK, int NCHUNK,
                                           int wt_off, int bn_off) {
    int n8    = li & 7;
    int kp    = (li >> 3) & 7;
    int j     = (li >> 6) & 7;
    int tap   = (li >> 9) % KK;
    int chunk = (li / (512 * KK)) % NCHUNK;
    int nb    = li / (512 * KK * NCHUNK);
    int oc  = nb * 64 + j * 8 + n8;
    int ic0 = chunk * 16 + kp * 2;
    float s = g_scale[bn_off + oc];
    float v0 = (ic0     < ICR) ? W[((size_t)oc * ICR + ic0)     * KK + tap] * s : 0.f;
    float v1 = (ic0 + 1 < ICR) ? W[((size_t)oc * ICR + ic0 + 1) * KK + tap] * s : 0.f;
    g_wt[wt_off + li] = h2pack(v0, v1);
}
// conv1 words: [ky7][p4][j4][kp4][n8]; k = kxl*4 + c (c=3 pad), kx = 2p+kxl
__global__ void wt_prep_all(const float* __restrict__ w1, const float* __restrict__ w2,
                            const float* __restrict__ w3, const float* __restrict__ wf1,
                            const float* __restrict__ wf2) {
    int i = blockIdx.x * blockDim.x + threadIdx.x;
    if (i < 3584) {
        int n8 = i & 7;
        int kp = (i >> 3) & 3;
        int j  = (i >> 5) & 3;
        int p  = (i >> 7) & 3;
        int ky = i >> 9;
        int oc = j * 8 + n8;
        float s = g_scale[oc];
        float vv[2];
#pragma unroll
        for (int t = 0; t < 2; t++) {
            int k   = kp * 2 + t;
            int kxl = k >> 2, c = k & 3;
            int kx  = 2 * p + kxl;
            vv[t] = (c < 3 && kx < 7) ? w1[oc * 147 + c * 49 + ky * 7 + kx] * s : 0.f;
        }
        g_wt[i] = h2pack(vv[0], vv[1]);
    } else if (i < 29184) {
        wt_generic(w2, i - 3584, 32, 25, 2, 3584, 32);
    } else if (i < 66048) {
        wt_generic(w3, i - 29184, 64, 9, 4, 29184, 96);
    } else if (i < 324096) {
        wt_generic(wf1, i - 66048, 209, 9, 14, 66048, 224);
    } else if (i < 619008) {
        wt_generic(wf2, i - 324096, 256, 9, 16, 324096, 480);
    }
}

// ------------------------- conv1 (7x7 s2, fp16 m16n8k8, 4ch-padded) --------
// 512 thr = 16 warps x 32 M-rows; block M=512 (16x32), N=32 (all oc).
__global__ void __launch_bounds__(512)
conv1_mma(const float* __restrict__ img0, const float* __restrict__ img1) {
    constexpr int INTH = 37, XSLOTS = 70;          // x 0..69 (kx=7 garbage in-bounds)
    constexpr int RSTRIDE = 140;                   // 2 words per x
    constexpr int SIN_SZ = INTH * RSTRIDE;         // 5180 words (mult of 4)
    constexpr int SW_SZ = 3584;

    extern __shared__ __align__(16) uint32 smem[];
    uint32* sIn = smem;
    uint32* sW  = smem + SIN_SZ;
    const uint32 smem_b = (uint32)__cvta_generic_to_shared(smem);

    const int tid  = threadIdx.x;
    const int lane = tid & 31;
    const int wid  = tid >> 5;

    const int b   = blockIdx.z;
    const int oh0 = blockIdx.y * 16;
    const int ow0 = blockIdx.x * 32;
    const int ir0 = oh0 * 2 - 3;
    const int ic0 = ow0 * 2 - 3;

    const float* in = (b < 32 ? img0 : img1) + (size_t)(b & 31) * 3 * 384 * 512;

    // async weight stage
    for (int i = tid; i < SW_SZ / 4; i += 512)
        cp_async16(smem_b + (SIN_SZ + i * 4) * 4, g_wt + i * 4);
    cp_commit();

    // stage input tile: word0=(c0,c1), word1=(c2,0)
    for (int i = tid; i < INTH * XSLOTS * 2; i += 512) {
        int w   = i & 1;
        int pix = i >> 1;
        int r   = pix / XSLOTS;
        int x   = pix % XSLOTS;
        int gr = ir0 + r, gc = ic0 + x;
        float v0 = 0.f, v1 = 0.f;
        if (gr >= 0 && gr < 384 && gc >= 0 && gc < 512) {
            if (w == 0) {
                v0 = in[(size_t)0 * 384 * 512 + (size_t)gr * 512 + gc];
                v1 = in[(size_t)1 * 384 * 512 + (size_t)gr * 512 + gc];
            } else {
                v0 = in[(size_t)2 * 384 * 512 + (size_t)gr * 512 + gc];
            }
        }
        sIn[r * RSTRIDE + x * 2 + w] = h2pack(v0, v1);
    }
    cp_wait0();
    __syncthreads();

    const int mgrp = wid * 32;
    const int q    = lane & 3;
    const int qoff = (q >> 1) * 2 + (q & 1);
    int abase[4];
#pragma unroll
    for (int r = 0; r < 4; r++) {
        int pm = mgrp + (lane >> 2) + 8 * r;
        abase[r] = (pm >> 5) * 280 + (pm & 31) * 4 + qoff;
    }
    const int bbase = q * 8 + (lane >> 2);

    float acc[2][4][4];
#pragma unroll
    for (int s = 0; s < 2; s++)
#pragma unroll
        for (int j = 0; j < 4; j++)
#pragma unroll
            for (int t = 0; t < 4; t++) acc[s][j][t] = 0.f;

#pragma unroll
    for (int ky = 0; ky < 7; ky++) {
#pragma unroll
        for (int p = 0; p < 4; p++) {
            const int off = ky * RSTRIDE + p * 4;
            uint32 A[4];
#pragma unroll
            for (int r = 0; r < 4; r++) A[r] = sIn[abase[r] + off];
            const int tb = ((ky * 4 + p) * 4) * 32;
#pragma unroll
            for (int j = 0; j < 4; j++) {
                uint32 B0 = sW[tb + j * 32 + bbase];
                mma_f16_k8(acc[0][j], A[0], A[1], B0);
                mma_f16_k8(acc[1][j], A[2], A[3], B0);
            }
        }
    }

    __half* outp = g_act1 + (size_t)b * 192 * 256 * 32;
#pragma unroll
    for (int s = 0; s < 2; s++) {
#pragma unroll
        for (int hr = 0; hr < 2; hr++) {
            int pm = mgrp + (lane >> 2) + 16 * s + 8 * hr;
            int goh = oh0 + (pm >> 5), gow = ow0 + (pm & 31);
#pragma unroll
            for (int j = 0; j < 4; j++) {
                int oc = j * 8 + (lane & 3) * 2;
                float v0 = fmaxf(acc[s][j][2 * hr]     + g_bias[oc],     0.f);
                float v1 = fmaxf(acc[s][j][2 * hr + 1] + g_bias[oc + 1], 0.f);
                *(uint32*)&outp[((size_t)goh * 256 + gow) * 32 + oc] = h2pack(v0, v1);
            }
        }
    }
}

// ------------------------- generic conv (fp16 m16n8k16, K-chunk 16) --------
// 512 thr = 16 warps = 8 M-groups x 2 N-groups. Block M=256, N=64.
template <int ICP, int OC, int K, int S, int P,
          int TOH, int TOW, int IH, int IW, int OH, int OW,
          int INBUF, int OUTBUF, bool OUT_F32>
__global__ void __launch_bounds__(512)
conv_mma(int wt_off, int bn_off) {
    constexpr int INTH    = (TOH - 1) * S + K;
    constexpr int INTW    = (TOW - 1) * S + K;
    constexpr int NPIX    = INTH * INTW;
    constexpr int NCHUNK  = ICP / 16;
    constexpr int NOCB    = OC / 64;
    constexpr int SIN_PAD = (NPIX * 10 + 3) & ~3;    // pixel = 8 words (16 f16) + 2 pad
    constexpr int SW_SZ   = K * K * 512;

    extern __shared__ __align__(16) uint32 smem[];
    const uint32 smem_b = (uint32)__cvta_generic_to_shared(smem);

    const int tid  = threadIdx.x;
    const int lane = tid & 31;
    const int wid  = tid >> 5;

    const int b   = blockIdx.z / NOCB;
    const int nb  = blockIdx.z % NOCB;
    const int oc0 = nb * 64;
    const int oh0 = blockIdx.y * TOH;
    const int ow0 = blockIdx.x * TOW;
    const int ir0 = oh0 * S - P;
    const int ic0 = ow0 * S - P;

    const __half* in_nhwc = get_buf_h(INBUF) + (size_t)b * IH * IW * ICP;
    const uint32* wt = g_wt + wt_off + (size_t)nb * NCHUNK * SW_SZ;

    float acc[2][4][4];
#pragma unroll
    for (int s = 0; s < 2; s++)
#pragma unroll
        for (int j = 0; j < 4; j++)
#pragma unroll
            for (int t = 0; t < 4; t++) acc[s][j][t] = 0.f;

    const int mgrp = (wid >> 1) * 32;
    const int ntg  = (wid & 1) * 4;
    int abase[4];
#pragma unroll
    for (int r = 0; r < 4; r++) {
        int pm = mgrp + (lane >> 2) + 8 * r;
        abase[r] = (((pm / TOW) * S) * INTW + (pm % TOW) * S) * 10 + (lane & 3);
    }
    const int bbase = (lane & 3) * 8 + (lane >> 2);

    auto do_mma = [&](const uint32* sInb, const uint32* sWb) {
#pragma unroll
        for (int ky = 0; ky < K; ky++) {
#pragma unroll
            for (int kx = 0; kx < K; kx++) {
                const int aoff = (ky * INTW + kx) * 10;
                uint32 Al[4], Ah[4];
#pragma unroll
                for (int r = 0; r < 4; r++) {
                    Al[r] = sInb[abase[r] + aoff];
                    Ah[r] = sInb[abase[r] + aoff + 4];
                }
                const int tapoff = (ky * K + kx) * 512;
#pragma unroll
                for (int j = 0; j < 4; j++) {
                    uint32 B0 = sWb[tapoff + (ntg + j) * 64 + bbase];
                    uint32 B1 = sWb[tapoff + (ntg + j) * 64 + bbase + 32];
                    mma_f16_k16(acc[0][j], Al[0], Al[1], Ah[0], Ah[1], B0, B1);
                    mma_f16_k16(acc[1][j], Al[2], Al[3], Ah[2], Ah[3], B0, B1);
                }
            }
        }
    };

    const int inO0 = 0, inO1 = SIN_PAD;
    const int wO0  = 2 * SIN_PAD, wO1 = 2 * SIN_PAD + SW_SZ;

    // pre-zero boundary pixels (both buffers; disjoint from cp.async targets)
    for (int pix = tid; pix < NPIX; pix += 512) {
        int r = pix / INTW, cc = pix % INTW;
        int gr = ir0 + r, gc = ic0 + cc;
        if (!(gr >= 0 && gr < IH && gc >= 0 && gc < IW)) {
#pragma unroll
            for (int c = 0; c < 8; c++) {
                smem[inO0 + pix * 10 + c] = 0;
                smem[inO1 + pix * 10 + c] = 0;
            }
        }
    }

    auto stage_in = [&](int chunk, int off) {
        const __half* base = in_nhwc + chunk * 16;
        for (int pix = tid; pix < NPIX; pix += 512) {
            int r = pix / INTW, cc = pix % INTW;
            int gr = ir0 + r, gc = ic0 + cc;
            if (gr >= 0 && gr < IH && gc >= 0 && gc < IW) {
                const __half* s = base + ((size_t)gr * IW + gc) * ICP;
                uint32 d = smem_b + (off + pix * 10) * 4;
                cp_async8(d,      s);
                cp_async8(d + 8,  s + 4);
                cp_async8(d + 16, s + 8);
                cp_async8(d + 24, s + 12);
            }
        }
    };
    auto stage_w = [&](int chunk, int off) {
        const uint32* s = wt + (size_t)chunk * SW_SZ;
        uint32 d = smem_b + off * 4;
        for (int i = tid; i < SW_SZ / 4; i += 512)
            cp_async16(d + i * 16, s + i * 4);
    };

    stage_in(0, inO0); stage_w(0, wO0); cp_commit();
    for (int ch = 0; ch < NCHUNK; ch++) {
        if (ch + 1 < NCHUNK) {
            int nxt = (ch + 1) & 1;
            stage_in(ch + 1, nxt ? inO1 : inO0);
            stage_w(ch + 1, nxt ? wO1 : wO0);
            cp_commit();
            cp_wait1();
        } else {
            cp_wait0();
        }
        __syncthreads();
        int cur = ch & 1;
        do_mma(smem + (cur ? inO1 : inO0), smem + (cur ? wO1 : wO0));
        __syncthreads();
    }

    // epilogue
#pragma unroll
    for (int s = 0; s < 2; s++) {
#pragma unroll
        for (int hr = 0; hr < 2; hr++) {
            int pm = mgrp + (lane >> 2) + 16 * s + 8 * hr;
            int goh = oh0 + pm / TOW, gow = ow0 + pm % TOW;
#pragma unroll
            for (int j = 0; j < 4; j++) {
                int oc = oc0 + (ntg + j) * 8 + (lane & 3) * 2;
                float v0 = fmaxf(acc[s][j][2 * hr]     + g_bias[bn_off + oc],     0.f);
                float v1 = fmaxf(acc[s][j][2 * hr + 1] + g_bias[bn_off + oc + 1], 0.f);
                if (OUT_F32) {
                    *(float2*)&g_y2[(((size_t)b * OH + goh) * OW + gow) * OC + oc] =
                        make_float2(v0, v1);
                } else {
                    __half* outp = get_buf_h(OUTBUF) + (size_t)b * OH * OW * OC;
                    *(uint32*)&outp[((size_t)goh * OW + gow) * OC + oc] = h2pack(v0, v1);
                }
            }
        }
    }
}

// ------------------------- per-pixel inverse L2 norm (half feat) -----------
__global__ void __launch_bounds__(256) l2inv_kernel() {
    int pix  = blockIdx.x * 8 + (threadIdx.x >> 5);
    int lane = threadIdx.x & 31;
    const __half2* p = (const __half2*)(g_feat + (size_t)pix * 128 + lane * 4);
    float2 a = __half22float2(p[0]);
    float2 c = __half22float2(p[1]);
    float ss = a.x * a.x + a.y * a.y + c.x * c.x + c.y * c.y;
#pragma unroll
    for (int o = 16; o > 0; o >>= 1) ss += __shfl_xor_sync(0xFFFFFFFFu, ss, o);
    if (lane == 0) g_inv[pix] = 1.0f / fmaxf(sqrtf(ss), 1e-12f);
}

// ------------------------- correlation volume ------------------------------
// grid (48,32), block 64; writes concat ch [0,81) as half.
__global__ void __launch_bounds__(64)
corr_kernel() {
    const int H = 48, W = 64;
    const int h = blockIdx.x;
    const int b = blockIdx.y;
    const int w = threadIdx.x;

    __shared__ float sF0[8 * 649];
    __shared__ float sF1[8 * 65];
    __shared__ float sInv0[9 * 72];
    __shared__ float sInv1[64];

    float acc[81];
#pragma unroll
    for (int o = 0; o < 81; o++) acc[o] = 0.f;

    const __half* f0b = g_feat + (size_t)b * H * W * 128;
    const __half* f1b = g_feat + (size_t)(b + 32) * H * W * 128;

    sInv1[w] = g_inv[((size_t)(b + 32) * H + h) * W + w];
    for (int i = w; i < 9 * 72; i += 64) {
        int r  = i / 72;
        int cc = i % 72;
        int gh = h + r - 4;
        int gw = cc - 4;
        float v = 0.f;
        if (gh >= 0 && gh < H && gw >= 0 && gw < W)
            v = g_inv[((size_t)b * H + gh) * W + gw];
        sInv0[i] = v;
    }
    __syncthreads();

    for (int c0 = 0; c0 < 128; c0 += 8) {
        for (int i = w; i < 8 * 64; i += 64) {
            int c = i & 7, ww = i >> 3;
            sF1[c * 65 + ww] = __half2float(f1b[((size_t)h * W + ww) * 128 + c0 + c]) * sInv1[ww];
        }
        for (int i = w; i < 8 * 648; i += 64) {
            int c   = i & 7;
            int pix = i >> 3;
            int r  = pix / 72;
            int cc = pix % 72;
            int gh = h + r - 4;
            int gw = cc - 4;
            float v = 0.f;
            if (gh >= 0 && gh < H && gw >= 0 && gw < W)
                v = __half2float(f0b[((size_t)gh * W + gw) * 128 + c0 + c]) * sInv0[pix];
            sF0[c * 649 + pix] = v;
        }
        __syncthreads();
#pragma unroll
        for (int c = 0; c < 8; c++) {
            float iv = sF1[c * 65 + w];
#pragma unroll
            for (int r = 0; r < 9; r++)
#pragma unroll
                for (int d = 0; d < 9; d++)
                    acc[r * 9 + d] = fmaf(sF0[c * 649 + r * 72 + w + d], iv, acc[r * 9 + d]);
        }
        __syncthreads();
    }
    __half* dst = g_concat + ((size_t)(b * H + h) * W + w) * 224;
#pragma unroll
    for (int o = 0; o < 81; o++) dst[o] = __float2half(acc[o]);
}

// ------------------------- f1 copy + pad into concat -----------------------
__global__ void copy_f1_kernel() {
    int i = blockIdx.x * 256 + threadIdx.x;     // over 32*48*64*143
    const int TOT = 32 * 48 * 64 * 143;
    if (i >= TOT) return;
    int c   = i % 143;
    int pix = i / 143;
    __half v = __float2half(0.f);
    if (c < 128) v = g_feat[((size_t)pix + (size_t)32 * 48 * 64) * 128 + c];
    g_concat[(size_t)pix * 224 + 81 + c] = v;
}

// ------------------------- global average pool -----------------------------
__global__ void __launch_bounds__(256)
avgpool_kernel(float* __restrict__ out) {
    int b = blockIdx.x;
    int c = threadIdx.x;
    const float* p = g_y2 + (size_t)b * 768 * 256 + c;
    float s = 0.f;
#pragma unroll 8
    for (int i = 0; i < 768; i++) s += p[(size_t)i * 256];
    out[b * 256 + c] = s * (1.0f / 768.0f);
}

// ---------------------------------------------------------------------------
extern "C" void kernel_launch(void* const* d_in, const int* in_sizes, int n_in,
                              void* d_out, int out_size) {
    (void)in_sizes; (void)n_in; (void)out_size;

    const float* img0 = (const float*)d_in[0];
    const float* img1 = (const float*)d_in[1];
    const float* w1 = (const float*)d_in[2];  const float* b1 = (const float*)d_in[3];
    const float* g1 = (const float*)d_in[4];  const float* be1 = (const float*)d_in[5];
    const float* m1 = (const float*)d_in[6];  const float* v1 = (const float*)d_in[7];
    const float* w2 = (const float*)d_in[8];  const float* b2 = (const float*)d_in[9];
    const float* g2 = (const float*)d_in[10]; const float* be2 = (const float*)d_in[11];
    const float* m2 = (const float*)d_in[12]; const float* v2 = (const float*)d_in[13];
    const float* w3 = (const float*)d_in[14]; const float* b3 = (const float*)d_in[15];
    const float* g3 = (const float*)d_in[16]; const float* be3 = (const float*)d_in[17];
    const float* m3 = (const float*)d_in[18]; const float* v3 = (const float*)d_in[19];
    const float* wf1 = (const float*)d_in[20]; const float* bf1 = (const float*)d_in[21];
    const float* gf1 = (const float*)d_in[22]; const float* bef1 = (const float*)d_in[23];
    const float* mf1 = (const float*)d_in[24]; const float* vf1 = (const float*)d_in[25];
    const float* wf2 = (const float*)d_in[26]; const float* bf2 = (const float*)d_in[27];
    const float* gf2 = (const float*)d_in[28]; const float* bef2 = (const float*)d_in[29];
    const float* mf2 = (const float*)d_in[30]; const float* vf2 = (const float*)d_in[31];

    // (1) BN fold
    bn_prep_all<<<3, 256>>>(g1, be1, m1, v1, b1, g2, be2, m2, v2, b2,
                            g3, be3, m3, v3, b3, gf1, bef1, mf1, vf1, bf1,
                            gf2, bef2, mf2, vf2, bf2);
    // (2) all weights, one launch
    wt_prep_all<<<(619008 + 255) / 256, 256>>>(w1, w2, w3, wf1, wf2);

    // (3) conv1
    {
        int sm = (5180 + 3584) * 4;                                       // 35,056
        cudaFuncSetAttribute(conv1_mma, cudaFuncAttributeMaxDynamicSharedMemorySize, sm);
        conv1_mma<<<dim3(8, 12, 64), 512, sm>>>(img0, img1);
    }
    // (4) conv2 — target of the profiler's capture slot
    {
        auto k = conv_mma<32, 64, 5, 2, 2, 16, 16, 192, 256, 96, 128, BUF_ACT1, BUF_ACT2, false>;
        int sm = 2 * ((((35 * 35 * 10) + 3) & ~3) + 25 * 512) * 4;        // 200,416
        cudaFuncSetAttribute(k, cudaFuncAttributeMaxDynamicSharedMemorySize, sm);
        k<<<dim3(8, 6, 64), 512, sm>>>(3584, 32);
    }
    // (5) conv3
    {
        auto k = conv_mma<64, 128, 3, 2, 1, 8, 32, 96, 128, 48, 64, BUF_ACT2, BUF_FEAT, false>;
        int sm = 2 * ((((17 * 65 * 10) + 3) & ~3) + 9 * 512) * 4;         // 125,280
        cudaFuncSetAttribute(k, cudaFuncAttributeMaxDynamicSharedMemorySize, sm);
        k<<<dim3(2, 6, 128), 512, sm>>>(29184, 96);
    }

    // (6) inverse L2 norms
    l2inv_kernel<<<(64 * 48 * 64) / 8, 256>>>();
    // (7) correlation, (8) f1 copy
    corr_kernel<<<dim3(48, 32), 64>>>();
    copy_f1_kernel<<<(32 * 48 * 64 * 143 + 255) / 256, 256>>>();

    // (9) convf1
    {
        auto k = conv_mma<224, 256, 3, 2, 1, 8, 32, 48, 64, 24, 32, BUF_CONCAT, BUF_Y1, false>;
        int sm = 2 * ((((17 * 65 * 10) + 3) & ~3) + 9 * 512) * 4;         // 125,280
        cudaFuncSetAttribute(k, cudaFuncAttributeMaxDynamicSharedMemorySize, sm);
        k<<<dim3(1, 3, 128), 512, sm>>>(66048, 224);
    }
    // (10) convf2 (f32 out)
    {
        auto k = conv_mma<256, 256, 3, 1, 1, 8, 32, 24, 32, 24, 32, BUF_Y1, BUF_Y2, true>;
        int sm = 2 * ((10 * 34 * 10) + 9 * 512) * 4;                      // 64,064
        cudaFuncSetAttribute(k, cudaFuncAttributeMaxDynamicSharedMemorySize, sm);
        k<<<dim3(1, 3, 128), 512, sm>>>(324096, 480);
    }

    // (11) global average pool -> (32,256)
    avgpool_kernel<<<32, 256>>>((float*)d_out);
}